// round 12
// baseline (speedup 1.0000x reference)
#include <cuda_runtime.h>
#include <cuda.h>
#include <cuda_fp16.h>
#include <math.h>
#include <stdint.h>

// Problem constants (fixed by setup_inputs)
#define Bv    16384
#define Cv    576          // N_CH*SIZE*SIZE
#define INFv  2304         // 4*Cv
#define HIDv  256
#define OUTFv 1152         // 2*Cv
#define Tv    20
#define INF2  1152         // fp32 state slices: [x | p]
#define NCTA  128

// Persistent scratch (device globals; no allocations allowed)
__device__ __align__(1024) float  g_inp [(size_t)Bv * INF2];     // fp32 [x | p]
__device__ __align__(1024) __half g_inph[(size_t)Bv * 2 * Cv];   // fp16 [y | z] ONLY
__device__ __align__(1024) __half g_devh[(size_t)Bv * OUTFv];    // [u_raw | v_raw] fp16
__device__ __align__(1024) __half g_W1h[(size_t)HIDv  * INFv];   // K-major [256,2304]
__device__ __align__(1024) __half g_W2h[(size_t)HIDv  * HIDv];
__device__ __align__(1024) __half g_W3h[(size_t)OUTFv * HIDv];
__device__ float g_res[Tv];
__device__ float g_del[Tv];
__device__ float g_Q  [Tv];

// ---------------------------------------------------------------------------
// PTX helpers
// ---------------------------------------------------------------------------
__device__ __forceinline__ uint32_t smem_to_u32(const void* p) {
    uint32_t a;
    asm("{ .reg .u64 t; cvta.to.shared.u64 t, %1; cvt.u32.u64 %0, t; }"
        : "=r"(a) : "l"(p));
    return a;
}

#define MBARRIER_INIT(addr, cnt) \
    asm volatile("mbarrier.init.shared.b64 [%0], %1;" :: "r"((uint32_t)(addr)), "r"((uint32_t)(cnt)) : "memory")
#define MBARRIER_ARRIVE(addr) \
    asm volatile("mbarrier.arrive.shared.b64 _, [%0];" :: "r"((uint32_t)(addr)) : "memory")
#define MBARRIER_EXPECT_TX(addr, bytes) \
    asm volatile("mbarrier.arrive.expect_tx.shared.b64 _, [%0], %1;" :: "r"((uint32_t)(addr)), "r"((uint32_t)(bytes)) : "memory")

#define MBARRIER_WAIT_PARITY(mbar, par) do { \
    uint32_t _m = (uint32_t)(mbar), _p = (uint32_t)(par), _d; \
    asm volatile("{\n\t.reg .pred p;\n\t" \
        "mbarrier.try_wait.parity.acquire.cta.shared::cta.b64 p, [%1], %2;\n\t" \
        "selp.b32 %0, 1, 0, p;\n\t}" : "=r"(_d) : "r"(_m), "r"(_p) : "memory"); \
    if (!_d) { \
        asm volatile("{\n\t.reg .pred P1;\n\t" \
            "W_%=:\n\t" \
            "mbarrier.try_wait.parity.acquire.cta.shared::cta.b64 P1, [%0], %1, 0x989680;\n\t" \
            "@P1 bra.uni D_%=;\n\tbra.uni W_%=;\n\tD_%=:\n\t}" \
            :: "r"(_m), "r"(_p) : "memory"); \
    } \
} while(0)

#define TMA_LOAD_2D(smem_addr, map_ptr, cx, cy, mbar) \
    asm volatile("cp.async.bulk.tensor.2d.shared::cta.global.tile.mbarrier::complete_tx::bytes " \
        "[%0], [%1, {%2, %3}], [%4];" \
        :: "r"((uint32_t)(smem_addr)), "l"(map_ptr), "r"((int32_t)(cx)), "r"((int32_t)(cy)), \
           "r"((uint32_t)(mbar)) : "memory")

#define FENCE_PROXY_ASYNC() asm volatile("fence.proxy.async;" ::: "memory")

#define BAR_SYNC(id, cnt) \
    asm volatile("bar.sync %0, %1;" :: "r"(id), "r"(cnt) : "memory")

#define LDMATRIX_X4(r0, r1, r2, r3, addr) \
    asm volatile("ldmatrix.sync.aligned.m8n8.x4.shared.b16 {%0,%1,%2,%3}, [%4];" \
        : "=r"(r0), "=r"(r1), "=r"(r2), "=r"(r3) : "r"(addr))

__device__ __forceinline__ void mma_f16(float* d, const uint32_t* a,
                                        uint32_t b0, uint32_t b1) {
    asm volatile(
        "mma.sync.aligned.m16n8k16.row.col.f32.f16.f16.f32 "
        "{%0,%1,%2,%3}, {%4,%5,%6,%7}, {%8,%9}, {%0,%1,%2,%3};"
        : "+f"(d[0]), "+f"(d[1]), "+f"(d[2]), "+f"(d[3])
        : "r"(a[0]), "r"(a[1]), "r"(a[2]), "r"(a[3]), "r"(b0), "r"(b1));
}

__device__ __forceinline__ float warp_sum(float v) {
    #pragma unroll
    for (int o = 16; o > 0; o >>= 1) v += __shfl_down_sync(0xffffffffu, v, o);
    return v;
}

// ---------------------------------------------------------------------------
// MEGA kernel, warp-specialized:
//   threads 0..511  : consumers (16 MMA warps)   — GEMM1+2+3
//   threads 512..575: producers (2 warps)        — step, A-ring fill
// SMEM: [bar 0..11][sred] APROD ring 2x64KB, BPIPE 2x32KB.
// Ring slot = 4 fp16 slices [128x64] (x,p,y,z) of one 64-col chunk.
// ---------------------------------------------------------------------------
__global__ void __launch_bounds__(576, 1)
mega(const __grid_constant__ CUtensorMap tmB1,
     const __grid_constant__ CUtensorMap tmB2,
     const __grid_constant__ CUtensorMap tmB3,
     const float* __restrict__ b1, const float* __restrict__ b2,
     const float* __restrict__ b3, int n)
{
    extern __shared__ char smem[];
    const uint32_t sb = smem_to_u32(smem);
    const int tid  = threadIdx.x;
    const int m0 = blockIdx.x * 128;

    const uint32_t BAR   = sb;                 // 12 mbarriers x 8B
    float* sred = (float*)(smem + 128);
    const uint32_t APROD = sb + 1024;          // 2 x 65536 ring
    const uint32_t BPIPE = APROD + 131072;     // 2 x 32768

    if (tid == 0) {
        #pragma unroll
        for (int s = 0; s < 12; ++s) MBARRIER_INIT(BAR + s * 8, 1);
        FENCE_PROXY_ASYNC();
    }
    __syncthreads();

    // Prologue: B1 stages q=0,1 (weights — independent of step)
    if (tid == 0) {
        #pragma unroll
        for (int q = 0; q < 2; ++q) {
            int kidx = (q & 3) * 9 + (q >> 2);
            MBARRIER_EXPECT_TX(BAR + (4 + q) * 8, 32768);
            TMA_LOAD_2D(BPIPE + q * 32768,         &tmB1, kidx * 64, 0,   BAR + (4 + q) * 8);
            TMA_LOAD_2D(BPIPE + q * 32768 + 16384, &tmB1, kidx * 64, 128, BAR + (4 + q) * 8);
        }
    }

    if (tid >= 512) {
        // =================== PRODUCER (2 warps, 64 threads) ===================
        const int pt   = tid - 512;
        const int lane = tid & 31;

        float al = 0.f;
        if (n > 0) {
            float delta = g_del[n - 1];
            float Q     = 1.5f * g_Q[n - 1] + 1e-12f;
            al = sqrtf(fminf(0.99f * fmaxf(delta, 0.f) / Q, 1.f));
        }
        const float a = (float)n / ((float)n + 3.f);

        float rsum = 0.f, dsum = 0.f;

        for (int j = 0; j < 9; ++j) {
            if (j >= 2)
                MBARRIER_WAIT_PARITY(BAR + (2 + (j & 1)) * 8, ((j >> 1) - 1) & 1);

            const uint32_t slot = APROD + (j & 1) * 65536;
            #pragma unroll
            for (int rr = 0; rr < 2; ++rr) {
                const int row = pt * 2 + rr;
                const int b   = m0 + row;
                float*  fr = g_inp  + (size_t)b * INF2   + j * 64;
                __half* hr = g_inph + (size_t)b * (2*Cv) + j * 64;
                const __half* orow = g_devh + (size_t)b * OUTFv + j * 64;
                const uint32_t abase = slot + row * 128;
                const int swrow = row & 7;

                #pragma unroll 2
                for (int g = 0; g < 8; ++g) {
                    const int c8 = g * 8;
                    float4 x0 = *(float4*)(fr + c8);
                    float4 x1 = *(float4*)(fr + c8 + 4);
                    float4 p0 = *(float4*)(fr + Cv + c8);
                    float4 p1 = *(float4*)(fr + Cv + c8 + 4);
                    uint4  yr = *(uint4*)(hr + c8);
                    uint4  zr = *(uint4*)(hr + Cv + c8);
                    uint4  ur = make_uint4(0,0,0,0), vr = make_uint4(0,0,0,0);
                    if (n > 0) {
                        ur = *(const uint4*)(orow + c8);
                        vr = *(const uint4*)(orow + Cv + c8);
                    }

                    float xs[8] = {x0.x,x0.y,x0.z,x0.w, x1.x,x1.y,x1.z,x1.w};
                    float ps[8] = {p0.x,p0.y,p0.z,p0.w, p1.x,p1.y,p1.z,p1.w};
                    float ys[8], zs[8], uu[8], vv[8];
                    {
                        const uint32_t* yw = (const uint32_t*)&yr;
                        const uint32_t* zw = (const uint32_t*)&zr;
                        const uint32_t* uw = (const uint32_t*)&ur;
                        const uint32_t* vw = (const uint32_t*)&vr;
                        #pragma unroll
                        for (int q = 0; q < 4; ++q) {
                            __half2 yh = *(__half2*)&yw[q];
                            __half2 zh = *(__half2*)&zw[q];
                            __half2 uh = *(__half2*)&uw[q];
                            __half2 vh = *(__half2*)&vw[q];
                            ys[2*q] = __low2float(yh); ys[2*q+1] = __high2float(yh);
                            zs[2*q] = __low2float(zh); zs[2*q+1] = __high2float(zh);
                            uu[2*q] = al * __low2float(uh); uu[2*q+1] = al * __high2float(uh);
                            vv[2*q] = al * __low2float(vh); vv[2*q+1] = al * __high2float(vh);
                        }
                    }

                    float xn[8], pr[8], yn[8], zn[8];
                    #pragma unroll
                    for (int e = 0; e < 8; ++e) {
                        float ynj = xs[e] + a * (ys[e] - xs[e]) + uu[e];
                        float zp  = a * (zs[e] - ps[e]);
                        float znj = xs[e] + a * (ps[e] - xs[e]) + zp + uu[e] + vv[e];
                        float zm  = znj - ynj;
                        float prj = copysignf(fmaxf(fabsf(zm) - 0.1f, 0.f), zm);
                        float xnj = xs[e] + (prj - znj) + zp;
                        xn[e] = xnj; pr[e] = prj; yn[e] = ynj; zn[e] = znj;
                        float r = prj - ynj; rsum += r * r;
                        float d = xnj - znj; dsum += d * d;
                    }

                    *(float4*)(fr + c8)          = make_float4(xn[0], xn[1], xn[2], xn[3]);
                    *(float4*)(fr + c8 + 4)      = make_float4(xn[4], xn[5], xn[6], xn[7]);
                    *(float4*)(fr + Cv + c8)     = make_float4(pr[0], pr[1], pr[2], pr[3]);
                    *(float4*)(fr + Cv + c8 + 4) = make_float4(pr[4], pr[5], pr[6], pr[7]);

                    uint4 hx, hp, hy, hz;
                    {
                        uint32_t* w;
                        w = (uint32_t*)&hx;
                        #pragma unroll
                        for (int q = 0; q < 4; ++q) *(__half2*)&w[q] = __floats2half2_rn(xn[2*q], xn[2*q+1]);
                        w = (uint32_t*)&hp;
                        #pragma unroll
                        for (int q = 0; q < 4; ++q) *(__half2*)&w[q] = __floats2half2_rn(pr[2*q], pr[2*q+1]);
                        w = (uint32_t*)&hy;
                        #pragma unroll
                        for (int q = 0; q < 4; ++q) *(__half2*)&w[q] = __floats2half2_rn(yn[2*q], yn[2*q+1]);
                        w = (uint32_t*)&hz;
                        #pragma unroll
                        for (int q = 0; q < 4; ++q) *(__half2*)&w[q] = __floats2half2_rn(zn[2*q], zn[2*q+1]);
                    }
                    *(uint4*)(hr + c8)      = hy;
                    *(uint4*)(hr + Cv + c8) = hz;

                    const uint32_t soff = abase + ((g ^ swrow) << 4);
                    asm volatile("st.shared.v4.b32 [%0], {%1,%2,%3,%4};"
                        :: "r"(soff), "r"(hx.x), "r"(hx.y), "r"(hx.z), "r"(hx.w));
                    asm volatile("st.shared.v4.b32 [%0], {%1,%2,%3,%4};"
                        :: "r"(soff + 16384), "r"(hp.x), "r"(hp.y), "r"(hp.z), "r"(hp.w));
                    asm volatile("st.shared.v4.b32 [%0], {%1,%2,%3,%4};"
                        :: "r"(soff + 32768), "r"(hy.x), "r"(hy.y), "r"(hy.z), "r"(hy.w));
                    asm volatile("st.shared.v4.b32 [%0], {%1,%2,%3,%4};"
                        :: "r"(soff + 49152), "r"(hz.x), "r"(hz.y), "r"(hz.z), "r"(hz.w));
                }
            }
            BAR_SYNC(1, 64);
            if (pt == 0) MBARRIER_ARRIVE(BAR + (j & 1) * 8);   // ring full
        }

        // res/del: per-warp reduce, atomics (2 warps)
        rsum = warp_sum(rsum); dsum = warp_sum(dsum);
        if (lane == 0) {
            atomicAdd(&g_res[n], rsum);
            atomicAdd(&g_del[n], dsum);
        }
        return;  // producers exit
    }

    // ===================== CONSUMER (16 warps, 512 threads) ====================
    const int wid  = tid >> 5;
    const int lane = tid & 31;
    const int warp_m = wid >> 2;
    const int warp_n = wid & 3;

    const int r_in = lane & 7;
    const int gA_m = ((lane >> 3) & 1) * 8;
    const int gA_u = (lane >> 4);
    const int gB_n = (lane >> 4) * 8;
    const int gB_u = ((lane >> 3) & 1);
    const int r_lo = lane >> 2;
    const int c_lo = lane & 3;

    float acc[2][8][4];
    #pragma unroll
    for (int mt = 0; mt < 2; ++mt)
        #pragma unroll
        for (int nt = 0; nt < 8; ++nt)
            #pragma unroll
            for (int q = 0; q < 4; ++q) acc[mt][nt][q] = 0.f;

    // ---- Phase 1: 9 chunks x 4 slices ----
    for (int j = 0; j < 9; ++j) {
        MBARRIER_WAIT_PARITY(BAR + (j & 1) * 8, (j >> 1) & 1);   // ring full
        const uint32_t slot = APROD + (j & 1) * 65536;

        #pragma unroll
        for (int s = 0; s < 4; ++s) {
            const int q = j * 4 + s;
            MBARRIER_WAIT_PARITY(BAR + (4 + (q & 1)) * 8, (q >> 1) & 1);
            const uint32_t As = slot + s * 16384;
            const uint32_t Bs = BPIPE + (q & 1) * 32768;

            #pragma unroll
            for (int kc = 0; kc < 4; ++kc) {
                uint32_t af[2][4];
                #pragma unroll
                for (int mt = 0; mt < 2; ++mt) {
                    int m = warp_m * 32 + mt * 16 + gA_m + r_in;
                    int u = kc * 2 + gA_u;
                    LDMATRIX_X4(af[mt][0], af[mt][1], af[mt][2], af[mt][3],
                                As + m * 128 + ((u ^ (m & 7)) << 4));
                }
                uint32_t bf[8][2];
                #pragma unroll
                for (int nt2 = 0; nt2 < 4; ++nt2) {
                    int nn = warp_n * 64 + nt2 * 16 + gB_n + r_in;
                    int u  = kc * 2 + gB_u;
                    LDMATRIX_X4(bf[2*nt2][0], bf[2*nt2][1], bf[2*nt2+1][0], bf[2*nt2+1][1],
                                Bs + nn * 128 + ((u ^ (nn & 7)) << 4));
                }
                #pragma unroll
                for (int mt = 0; mt < 2; ++mt)
                    #pragma unroll
                    for (int nt = 0; nt < 8; ++nt)
                        mma_f16(acc[mt][nt], af[mt], bf[nt][0], bf[nt][1]);
            }
            BAR_SYNC(2, 512);
            if (tid == 0) {
                int nq = q + 2;
                if (nq < 36) {
                    int kidx = (nq & 3) * 9 + (nq >> 2);
                    MBARRIER_EXPECT_TX(BAR + (4 + (nq & 1)) * 8, 32768);
                    TMA_LOAD_2D(BPIPE + (nq & 1) * 32768,         &tmB1, kidx * 64, 0,   BAR + (4 + (nq & 1)) * 8);
                    TMA_LOAD_2D(BPIPE + (nq & 1) * 32768 + 16384, &tmB1, kidx * 64, 128, BAR + (4 + (nq & 1)) * 8);
                }
            }
        }
        if (tid == 0) {
            MBARRIER_ARRIVE(BAR + (2 + (j & 1)) * 8);   // ring empty
            if (j == 7) {   // slot1 free forever -> W2 chunks 0,1 into APROD+65536
                #pragma unroll
                for (int c = 0; c < 2; ++c) {
                    MBARRIER_EXPECT_TX(BAR + (6 + c) * 8, 32768);
                    TMA_LOAD_2D(APROD + 65536 + c * 32768,         &tmB2, c * 64, 0,   BAR + (6 + c) * 8);
                    TMA_LOAD_2D(APROD + 65536 + c * 32768 + 16384, &tmB2, c * 64, 128, BAR + (6 + c) * 8);
                }
            }
        }
    }

    // W2 chunks 2,3 into BPIPE (B1 fully consumed)
    if (tid == 0) {
        #pragma unroll
        for (int c = 2; c < 4; ++c) {
            MBARRIER_EXPECT_TX(BAR + (6 + c) * 8, 32768);
            TMA_LOAD_2D(BPIPE + (c - 2) * 32768,         &tmB2, c * 64, 0,   BAR + (6 + c) * 8);
            TMA_LOAD_2D(BPIPE + (c - 2) * 32768 + 16384, &tmB2, c * 64, 128, BAR + (6 + c) * 8);
        }
    }

    // ---- h1 -> SMEM chunks at APROD (slot0 region) ----
    #pragma unroll
    for (int nt = 0; nt < 8; ++nt) {
        const int col = warp_n * 64 + nt * 8 + c_lo * 2;
        const float bias0 = b1[col], bias1 = b1[col + 1];
        #pragma unroll
        for (int mt = 0; mt < 2; ++mt) {
            const int mrow0 = warp_m * 32 + mt * 16 + r_lo;
            float v0 = fmaxf(acc[mt][nt][0] + bias0, 0.f);
            float v1 = fmaxf(acc[mt][nt][1] + bias1, 0.f);
            float v2 = fmaxf(acc[mt][nt][2] + bias0, 0.f);
            float v3 = fmaxf(acc[mt][nt][3] + bias1, 0.f);
            char* base = smem + 1024 + warp_n * 16384;
            *(__half2*)(base + mrow0 * 128 + ((nt ^ (mrow0 & 7)) << 4) + c_lo * 4) =
                __floats2half2_rn(v0, v1);
            int mrow1 = mrow0 + 8;
            *(__half2*)(base + mrow1 * 128 + ((nt ^ (mrow1 & 7)) << 4) + c_lo * 4) =
                __floats2half2_rn(v2, v3);
        }
    }
    #pragma unroll
    for (int mt = 0; mt < 2; ++mt)
        #pragma unroll
        for (int nt = 0; nt < 8; ++nt)
            #pragma unroll
            for (int q = 0; q < 4; ++q) acc[mt][nt][q] = 0.f;
    BAR_SYNC(2, 512);

    // ---- Phase 2: h2 = relu(h1 @ W2^T + b2) ----
    #pragma unroll
    for (int kc2 = 0; kc2 < 4; ++kc2) {
        MBARRIER_WAIT_PARITY(BAR + (6 + kc2) * 8, 0);
        const uint32_t As2 = APROD + kc2 * 16384;
        const uint32_t Bs2 = (kc2 < 2) ? (APROD + 65536 + kc2 * 32768)
                                       : (BPIPE + (kc2 - 2) * 32768);
        #pragma unroll
        for (int kc = 0; kc < 4; ++kc) {
            uint32_t af[2][4];
            #pragma unroll
            for (int mt = 0; mt < 2; ++mt) {
                int m = warp_m * 32 + mt * 16 + gA_m + r_in;
                int u = kc * 2 + gA_u;
                LDMATRIX_X4(af[mt][0], af[mt][1], af[mt][2], af[mt][3],
                            As2 + m * 128 + ((u ^ (m & 7)) << 4));
            }
            uint32_t bf[8][2];
            #pragma unroll
            for (int nt2 = 0; nt2 < 4; ++nt2) {
                int nn = warp_n * 64 + nt2 * 16 + gB_n + r_in;
                int u  = kc * 2 + gB_u;
                LDMATRIX_X4(bf[2*nt2][0], bf[2*nt2][1], bf[2*nt2+1][0], bf[2*nt2+1][1],
                            Bs2 + nn * 128 + ((u ^ (nn & 7)) << 4));
            }
            #pragma unroll
            for (int mt = 0; mt < 2; ++mt)
                #pragma unroll
                for (int nt = 0; nt < 8; ++nt)
                    mma_f16(acc[mt][nt], af[mt], bf[nt][0], bf[nt][1]);
        }
    }
    BAR_SYNC(2, 512);

    // ---- W3 chunks 0,1 (buffers: APROD+65536 / BPIPE, 64KB each) ----
    if (tid == 0) {
        #pragma unroll
        for (int c = 0; c < 2; ++c) {
            const uint32_t dst = (c == 0) ? (APROD + 65536) : BPIPE;
            MBARRIER_EXPECT_TX(BAR + (10 + c) * 8, 65536);
            #pragma unroll
            for (int jj = 0; jj < 4; ++jj)
                TMA_LOAD_2D(dst + jj * 16384, &tmB3, jj * 64, c * 128, BAR + (10 + c) * 8);
        }
    }

    // ---- h2 -> SMEM chunks (overwrite h1) ----
    #pragma unroll
    for (int nt = 0; nt < 8; ++nt) {
        const int col = warp_n * 64 + nt * 8 + c_lo * 2;
        const float bias0 = b2[col], bias1 = b2[col + 1];
        #pragma unroll
        for (int mt = 0; mt < 2; ++mt) {
            const int mrow0 = warp_m * 32 + mt * 16 + r_lo;
            float v0 = fmaxf(acc[mt][nt][0] + bias0, 0.f);
            float v1 = fmaxf(acc[mt][nt][1] + bias1, 0.f);
            float v2 = fmaxf(acc[mt][nt][2] + bias0, 0.f);
            float v3 = fmaxf(acc[mt][nt][3] + bias1, 0.f);
            char* base = smem + 1024 + warp_n * 16384;
            *(__half2*)(base + mrow0 * 128 + ((nt ^ (mrow0 & 7)) << 4) + c_lo * 4) =
                __floats2half2_rn(v0, v1);
            int mrow1 = mrow0 + 8;
            *(__half2*)(base + mrow1 * 128 + ((nt ^ (mrow1 & 7)) << 4) + c_lo * 4) =
                __floats2half2_rn(v2, v3);
        }
    }
    BAR_SYNC(2, 512);

    // ---- Phase 3: dev = h2 @ W3^T + b3, 9 n-chunks, Q-sum ----
    float qs = 0.f;
    for (int c = 0; c < 9; ++c) {
        const int bsel = c & 1;
        MBARRIER_WAIT_PARITY(BAR + (10 + bsel) * 8, (c >> 1) & 1);

        float a3[2][4][4];
        #pragma unroll
        for (int mt = 0; mt < 2; ++mt)
            #pragma unroll
            for (int nt = 0; nt < 4; ++nt)
                #pragma unroll
                for (int q = 0; q < 4; ++q) a3[mt][nt][q] = 0.f;

        const uint32_t Bs3 = (bsel == 0) ? (APROD + 65536) : BPIPE;
        #pragma unroll
        for (int kk = 0; kk < 4; ++kk) {
            const uint32_t As3 = APROD + kk * 16384;
            const uint32_t Bk3 = Bs3 + kk * 16384;
            #pragma unroll
            for (int kc = 0; kc < 4; ++kc) {
                uint32_t af[2][4];
                #pragma unroll
                for (int mt = 0; mt < 2; ++mt) {
                    int m = warp_m * 32 + mt * 16 + gA_m + r_in;
                    int u = kc * 2 + gA_u;
                    LDMATRIX_X4(af[mt][0], af[mt][1], af[mt][2], af[mt][3],
                                As3 + m * 128 + ((u ^ (m & 7)) << 4));
                }
                uint32_t bf[4][2];
                #pragma unroll
                for (int nt2 = 0; nt2 < 2; ++nt2) {
                    int nn = warp_n * 32 + nt2 * 16 + gB_n + r_in;
                    int u  = kc * 2 + gB_u;
                    LDMATRIX_X4(bf[2*nt2][0], bf[2*nt2][1], bf[2*nt2+1][0], bf[2*nt2+1][1],
                                Bk3 + nn * 128 + ((u ^ (nn & 7)) << 4));
                }
                #pragma unroll
                for (int mt = 0; mt < 2; ++mt)
                    #pragma unroll
                    for (int nt = 0; nt < 4; ++nt)
                        mma_f16(a3[mt][nt], af[mt], bf[nt][0], bf[nt][1]);
            }
        }

        #pragma unroll
        for (int nt = 0; nt < 4; ++nt) {
            const int col = c * 128 + warp_n * 32 + nt * 8 + c_lo * 2;
            const float bias0 = b3[col], bias1 = b3[col + 1];
            #pragma unroll
            for (int mt = 0; mt < 2; ++mt) {
                const int row0 = m0 + warp_m * 32 + mt * 16 + r_lo;
                float v0 = a3[mt][nt][0] + bias0;
                float v1 = a3[mt][nt][1] + bias1;
                float v2 = a3[mt][nt][2] + bias0;
                float v3 = a3[mt][nt][3] + bias1;
                qs += v0 * v0 + v1 * v1 + v2 * v2 + v3 * v3;
                *(__half2*)(g_devh + (size_t)row0 * OUTFv + col)       = __floats2half2_rn(v0, v1);
                *(__half2*)(g_devh + (size_t)(row0 + 8) * OUTFv + col) = __floats2half2_rn(v2, v3);
            }
        }
        BAR_SYNC(2, 512);
        if (tid == 0 && c + 2 < 9) {
            const uint32_t dst = (bsel == 0) ? (APROD + 65536) : BPIPE;
            MBARRIER_EXPECT_TX(BAR + (10 + bsel) * 8, 65536);
            #pragma unroll
            for (int jj = 0; jj < 4; ++jj)
                TMA_LOAD_2D(dst + jj * 16384, &tmB3, jj * 64, (c + 2) * 128, BAR + (10 + bsel) * 8);
        }
    }

    // ---- Q block reduction (consumers only) ----
    qs = warp_sum(qs);
    if (lane == 0) sred[wid] = qs;
    BAR_SYNC(2, 512);
    if (wid == 0) {
        float t = (lane < 16) ? sred[lane] : 0.f;
        t = warp_sum(t);
        if (lane == 0) atomicAdd(&g_Q[n], t);
    }
}

// ---------------------------------------------------------------------------
// Weight transpose to fp16 K-major
// ---------------------------------------------------------------------------
__global__ void transpose_kernel(const float* __restrict__ W, __half* __restrict__ Wt,
                                 int K, int N)
{
    __shared__ float t[32][33];
    int k0 = blockIdx.x * 32, n0 = blockIdx.y * 32;
    int x = threadIdx.x, y0 = threadIdx.y;
    #pragma unroll
    for (int dy = 0; dy < 32; dy += 8) {
        int k = k0 + y0 + dy, n = n0 + x;
        if (k < K && n < N) t[y0 + dy][x] = W[(size_t)k * N + n];
    }
    __syncthreads();
    #pragma unroll
    for (int dy = 0; dy < 32; dy += 8) {
        int n = n0 + y0 + dy, k = k0 + x;
        if (n < N && k < K) Wt[(size_t)n * K + k] = __float2half_rn(t[x][y0 + dy]);
    }
}

// ---------------------------------------------------------------------------
// init / finalize
// ---------------------------------------------------------------------------
__global__ void __launch_bounds__(512)
init_kernel(const float* __restrict__ noisy) {
    int i = blockIdx.x * 512 + threadIdx.x;       // vec8 index, total Bv*72
    if (i < Tv) { g_res[i] = 0.f; g_del[i] = 0.f; g_Q[i] = 0.f; }
    int b = i / 72, c8 = (i - b * 72) * 8;
    float4 v0 = make_float4(0.f, 0.f, 0.f, 0.f), v1 = v0;
    if (c8 < 64) {
        v0 = *(const float4*)(noisy + b * 64 + c8);
        v1 = *(const float4*)(noisy + b * 64 + c8 + 4);
    }
    float* frow = g_inp + (size_t)b * INF2;
    *(float4*)(frow + c8)          = v0;
    *(float4*)(frow + c8 + 4)      = v1;
    *(float4*)(frow + Cv + c8)     = v0;
    *(float4*)(frow + Cv + c8 + 4) = v1;
    __half* hrow = g_inph + (size_t)b * (2*Cv);
    uint4 h;
    *(__half2*)&h.x = __floats2half2_rn(v0.x, v0.y);
    *(__half2*)&h.y = __floats2half2_rn(v0.z, v0.w);
    *(__half2*)&h.z = __floats2half2_rn(v1.x, v1.y);
    *(__half2*)&h.w = __floats2half2_rn(v1.z, v1.w);
    *(uint4*)(hrow + c8)      = h;   // y
    *(uint4*)(hrow + Cv + c8) = h;   // z
}

__global__ void __launch_bounds__(512)
finalize_kernel(float* __restrict__ out) {
    int i = blockIdx.x * 512 + threadIdx.x;
    int b = i / 72, c8 = (i - b * 72) * 8;
    const float* src = g_inp + (size_t)b * INF2 + Cv + c8;
    float4 v0 = *(const float4*)(src);
    float4 v1 = *(const float4*)(src + 4);
    *(float4*)(out + (size_t)b * Cv + c8)     = v0;
    *(float4*)(out + (size_t)b * Cv + c8 + 4) = v1;
    if (i < Tv) out[(size_t)Bv * Cv + i] = sqrtf(g_res[i] + 1e-12f);
}

// ---------------------------------------------------------------------------
// Host side
// ---------------------------------------------------------------------------
typedef CUresult (*EncodeFn)(CUtensorMap*, CUtensorMapDataType, cuuint32_t, void*,
                             const cuuint64_t*, const cuuint64_t*, const cuuint32_t*,
                             const cuuint32_t*, CUtensorMapInterleave, CUtensorMapSwizzle,
                             CUtensorMapL2promotion, CUtensorMapFloatOOBfill);

static void make_map_h(EncodeFn enc, CUtensorMap* tm, void* base, int Kdim, int rows) {
    cuuint64_t dims[2]    = {(cuuint64_t)Kdim, (cuuint64_t)rows};
    cuuint64_t strides[1] = {(cuuint64_t)Kdim * 2};
    cuuint32_t box[2]     = {64u, 128u};
    cuuint32_t es[2]      = {1u, 1u};
    enc(tm, CU_TENSOR_MAP_DATA_TYPE_FLOAT16, 2, base, dims, strides, box, es,
        CU_TENSOR_MAP_INTERLEAVE_NONE, CU_TENSOR_MAP_SWIZZLE_128B,
        CU_TENSOR_MAP_L2_PROMOTION_L2_128B, CU_TENSOR_MAP_FLOAT_OOB_FILL_NONE);
}

extern "C" void kernel_launch(void* const* d_in, const int* in_sizes, int n_in,
                              void* d_out, int out_size) {
    const float* noisy = (const float*)d_in[0];
    const float* W1 = (const float*)d_in[1];
    const float* b1 = (const float*)d_in[2];
    const float* W2 = (const float*)d_in[3];
    const float* b2 = (const float*)d_in[4];
    const float* W3 = (const float*)d_in[5];
    const float* b3 = (const float*)d_in[6];
    float* out = (float*)d_out;

    __half *W1h, *W2h, *W3h;
    cudaGetSymbolAddress((void**)&W1h, g_W1h);
    cudaGetSymbolAddress((void**)&W2h, g_W2h);
    cudaGetSymbolAddress((void**)&W3h, g_W3h);

    static EncodeFn enc = nullptr;
    if (!enc) {
        void* p = nullptr;
        cudaDriverEntryPointQueryResult st;
        cudaGetDriverEntryPoint("cuTensorMapEncodeTiled", &p, cudaEnableDefault, &st);
        enc = (EncodeFn)p;
    }

    CUtensorMap tB1, tB2, tB3;
    make_map_h(enc, &tB1, W1h, INFv, HIDv);
    make_map_h(enc, &tB2, W2h, HIDv, HIDv);
    make_map_h(enc, &tB3, W3h, HIDv, OUTFv);

    const int SMEM_SZ = 1024 + 131072 + 65536;   // 197632
    static bool attr_set = false;
    if (!attr_set) {
        cudaFuncSetAttribute(mega, cudaFuncAttributeMaxDynamicSharedMemorySize, SMEM_SZ);
        attr_set = true;
    }

    dim3 tb(32, 8);
    transpose_kernel<<<dim3(INFv/32, HIDv/32),  tb>>>(W1, W1h, INFv, HIDv);
    transpose_kernel<<<dim3(HIDv/32, HIDv/32),  tb>>>(W2, W2h, HIDv, HIDv);
    transpose_kernel<<<dim3(HIDv/32, OUTFv/32), tb>>>(W3, W3h, HIDv, OUTFv);

    const int VBLK8 = (Bv * 72) / 512;   // 2304
    init_kernel<<<VBLK8, 512>>>(noisy);

    for (int n = 0; n < Tv; ++n)
        mega<<<NCTA, 576, SMEM_SZ>>>(tB1, tB2, tB3, b1, b2, b3, n);

    finalize_kernel<<<VBLK8, 512>>>(out);
}

// round 13
// speedup vs baseline: 1.4775x; 1.4775x over previous
#include <cuda_runtime.h>
#include <cuda.h>
#include <cuda_fp16.h>
#include <math.h>
#include <stdint.h>

// Problem constants (fixed by setup_inputs)
#define Bv    16384
#define Cv    576          // N_CH*SIZE*SIZE
#define INFv  2304         // 4*Cv
#define HIDv  256
#define OUTFv 1152         // 2*Cv
#define Tv    20
#define INF2  1152         // fp32 state slices: [x | p]
#define NCTA  128          // fused123 CTAs (row-blocks)
#define SUBS  36           // step sub-blocks per row-block (256 thr each)

// Persistent scratch (device globals; no allocations allowed)
__device__ __align__(1024) float  g_inp [(size_t)Bv * INF2];   // fp32 [x | p]
__device__ __align__(1024) __half g_inph[(size_t)Bv * INFv];   // fp16 mirror [x|p|y|z]
__device__ __align__(1024) __half g_devh[(size_t)Bv * OUTFv];  // [u_raw | v_raw] fp16
__device__ __align__(1024) __half g_W1h[(size_t)HIDv  * INFv]; // K-major [256,2304]
__device__ __align__(1024) __half g_W2h[(size_t)HIDv  * HIDv];
__device__ __align__(1024) __half g_W3h[(size_t)OUTFv * HIDv];
__device__ float g_res[Tv];
__device__ float g_del[Tv];
__device__ float g_Q  [Tv];
__device__ int   g_flag[Tv * NCTA];   // per-(iter,row-block) step completion

// ---------------------------------------------------------------------------
// PTX helpers
// ---------------------------------------------------------------------------
__device__ __forceinline__ uint32_t smem_to_u32(const void* p) {
    uint32_t a;
    asm("{ .reg .u64 t; cvta.to.shared.u64 t, %1; cvt.u32.u64 %0, t; }"
        : "=r"(a) : "l"(p));
    return a;
}

#define MBARRIER_INIT(addr, cnt) \
    asm volatile("mbarrier.init.shared.b64 [%0], %1;" :: "r"((uint32_t)(addr)), "r"((uint32_t)(cnt)) : "memory")
#define MBARRIER_EXPECT_TX(addr, bytes) \
    asm volatile("mbarrier.arrive.expect_tx.shared.b64 _, [%0], %1;" :: "r"((uint32_t)(addr)), "r"((uint32_t)(bytes)) : "memory")

#define MBARRIER_WAIT_PARITY(mbar, par) do { \
    uint32_t _m = (uint32_t)(mbar), _p = (uint32_t)(par), _d; \
    asm volatile("{\n\t.reg .pred p;\n\t" \
        "mbarrier.try_wait.parity.acquire.cta.shared::cta.b64 p, [%1], %2;\n\t" \
        "selp.b32 %0, 1, 0, p;\n\t}" : "=r"(_d) : "r"(_m), "r"(_p) : "memory"); \
    if (!_d) { \
        asm volatile("{\n\t.reg .pred P1;\n\t" \
            "W_%=:\n\t" \
            "mbarrier.try_wait.parity.acquire.cta.shared::cta.b64 P1, [%0], %1, 0x989680;\n\t" \
            "@P1 bra.uni D_%=;\n\tbra.uni W_%=;\n\tD_%=:\n\t}" \
            :: "r"(_m), "r"(_p) : "memory"); \
    } \
} while(0)

#define TMA_LOAD_2D(smem_addr, map_ptr, cx, cy, mbar) \
    asm volatile("cp.async.bulk.tensor.2d.shared::cta.global.tile.mbarrier::complete_tx::bytes " \
        "[%0], [%1, {%2, %3}], [%4];" \
        :: "r"((uint32_t)(smem_addr)), "l"(map_ptr), "r"((int32_t)(cx)), "r"((int32_t)(cy)), \
           "r"((uint32_t)(mbar)) : "memory")

#define FENCE_PROXY_ASYNC() asm volatile("fence.proxy.async;" ::: "memory")

#define LDMATRIX_X4(r0, r1, r2, r3, addr) \
    asm volatile("ldmatrix.sync.aligned.m8n8.x4.shared.b16 {%0,%1,%2,%3}, [%4];" \
        : "=r"(r0), "=r"(r1), "=r"(r2), "=r"(r3) : "r"(addr))

__device__ __forceinline__ void mma_f16(float* d, const uint32_t* a,
                                        uint32_t b0, uint32_t b1) {
    asm volatile(
        "mma.sync.aligned.m16n8k16.row.col.f32.f16.f16.f32 "
        "{%0,%1,%2,%3}, {%4,%5,%6,%7}, {%8,%9}, {%0,%1,%2,%3};"
        : "+f"(d[0]), "+f"(d[1]), "+f"(d[2]), "+f"(d[3])
        : "r"(a[0]), "r"(a[1]), "r"(a[2]), "r"(a[3]), "r"(b0), "r"(b1));
}

__device__ __forceinline__ float warp_sum(float v) {
    #pragma unroll
    for (int o = 16; o > 0; o >>= 1) v += __shfl_down_sync(0xffffffffu, v, o);
    return v;
}

__device__ __forceinline__ int ld_volatile_i32(const int* p) {
    int v;
    asm volatile("ld.volatile.global.s32 %0, [%1];" : "=r"(v) : "l"(p));
    return v;
}

// ---------------------------------------------------------------------------
// FUSED GEMM1+GEMM2+GEMM3 + per-row-block flag spin at entry.
// Runs on a second stream, overlapping the step kernel of the SAME iteration.
// ---------------------------------------------------------------------------
__global__ void __launch_bounds__(512, 1)
fused123(const __grid_constant__ CUtensorMap tmA,
         const __grid_constant__ CUtensorMap tmB1,
         const __grid_constant__ CUtensorMap tmB2,
         const __grid_constant__ CUtensorMap tmB3,
         const float* __restrict__ b1, const float* __restrict__ b2,
         const float* __restrict__ b3,
         __half* __restrict__ dev, float* __restrict__ Qacc, int n)
{
    constexpr int STAGES  = 4;
    constexpr int A_BYTES = 128 * 64 * 2;
    constexpr int B_BYTES = 256 * 64 * 2;
    constexpr int STAGE_B = A_BYTES + B_BYTES;
    constexpr int NITER   = INFv / 64;        // 36

    extern __shared__ char smem[];
    const uint32_t sb = smem_to_u32(smem);
    const int tid  = threadIdx.x;
    const int wid  = tid >> 5;
    const int lane = tid & 31;
    const int warp_m = wid >> 2;
    const int warp_n = wid & 3;
    const int m0 = blockIdx.x * 128;

    const uint32_t FULLB = sb;                // 8 mbarriers
    float* sred = (float*)(smem + 128);
    const uint32_t TILE  = sb + 1024;
    const uint32_t W2S   = TILE + 65536;

    // ---- wait for this row-block's step to finish (SUBS sub-blocks) ----
    if (tid == 0) {
        while (ld_volatile_i32(&g_flag[n * NCTA + blockIdx.x]) < SUBS) { }
        __threadfence();
        #pragma unroll
        for (int s = 0; s < 8; ++s) MBARRIER_INIT(FULLB + s * 8, 1);
        FENCE_PROXY_ASYNC();
    }
    __syncthreads();

    if (tid == 0) {
        #pragma unroll
        for (int s = 0; s < STAGES - 1; ++s) {
            MBARRIER_EXPECT_TX(FULLB + s * 8, STAGE_B);
            TMA_LOAD_2D(TILE + s * STAGE_B, &tmA, s * 64, m0, FULLB + s * 8);
            TMA_LOAD_2D(TILE + s * STAGE_B + A_BYTES,         &tmB1, s * 64, 0,   FULLB + s * 8);
            TMA_LOAD_2D(TILE + s * STAGE_B + A_BYTES + 16384, &tmB1, s * 64, 128, FULLB + s * 8);
        }
    }

    float acc[2][8][4];
    #pragma unroll
    for (int mt = 0; mt < 2; ++mt)
        #pragma unroll
        for (int nt = 0; nt < 8; ++nt)
            #pragma unroll
            for (int q = 0; q < 4; ++q) acc[mt][nt][q] = 0.f;

    const int r_in = lane & 7;
    const int gA_m = ((lane >> 3) & 1) * 8;
    const int gA_u = (lane >> 4);
    const int gB_n = (lane >> 4) * 8;
    const int gB_u = ((lane >> 3) & 1);

    // ---- Phase 1 ----
    for (int it = 0; it < NITER; ++it) {
        const int s = it % STAGES;
        MBARRIER_WAIT_PARITY(FULLB + s * 8, (it / STAGES) & 1);

        if (tid == 0) {
            int nx = it + STAGES - 1;
            if (nx < NITER) {
                int sx = nx % STAGES;
                MBARRIER_EXPECT_TX(FULLB + sx * 8, STAGE_B);
                TMA_LOAD_2D(TILE + sx * STAGE_B, &tmA, nx * 64, m0, FULLB + sx * 8);
                TMA_LOAD_2D(TILE + sx * STAGE_B + A_BYTES,         &tmB1, nx * 64, 0,   FULLB + sx * 8);
                TMA_LOAD_2D(TILE + sx * STAGE_B + A_BYTES + 16384, &tmB1, nx * 64, 128, FULLB + sx * 8);
            }
        }

        const uint32_t As = TILE + s * STAGE_B;
        const uint32_t Bs = As + A_BYTES;

        #pragma unroll
        for (int kc = 0; kc < 4; ++kc) {
            uint32_t af[2][4];
            #pragma unroll
            for (int mt = 0; mt < 2; ++mt) {
                int m = warp_m * 32 + mt * 16 + gA_m + r_in;
                int u = kc * 2 + gA_u;
                LDMATRIX_X4(af[mt][0], af[mt][1], af[mt][2], af[mt][3],
                            As + m * 128 + ((u ^ (m & 7)) << 4));
            }
            uint32_t bf[8][2];
            #pragma unroll
            for (int nt2 = 0; nt2 < 4; ++nt2) {
                int nn = warp_n * 64 + nt2 * 16 + gB_n + r_in;
                int u  = kc * 2 + gB_u;
                LDMATRIX_X4(bf[2*nt2][0], bf[2*nt2][1], bf[2*nt2+1][0], bf[2*nt2+1][1],
                            Bs + nn * 128 + ((u ^ (nn & 7)) << 4));
            }
            #pragma unroll
            for (int mt = 0; mt < 2; ++mt)
                #pragma unroll
                for (int nt = 0; nt < 8; ++nt)
                    mma_f16(acc[mt][nt], af[mt], bf[nt][0], bf[nt][1]);
        }
        __syncthreads();
    }

    // ---- W2 prefetch ----
    if (tid == 0) {
        #pragma unroll
        for (int kc2 = 0; kc2 < 4; ++kc2) {
            MBARRIER_EXPECT_TX(FULLB + (4 + kc2) * 8, 32768);
            TMA_LOAD_2D(W2S + kc2 * 32768,         &tmB2, kc2 * 64, 0,   FULLB + (4 + kc2) * 8);
            TMA_LOAD_2D(W2S + kc2 * 32768 + 16384, &tmB2, kc2 * 64, 128, FULLB + (4 + kc2) * 8);
        }
    }

    // ---- h1 -> SMEM chunks ----
    {
        const int r_lo = lane >> 2;
        const int c_lo = lane & 3;
        #pragma unroll
        for (int nt = 0; nt < 8; ++nt) {
            const int col = warp_n * 64 + nt * 8 + c_lo * 2;
            const float bias0 = b1[col], bias1 = b1[col + 1];
            #pragma unroll
            for (int mt = 0; mt < 2; ++mt) {
                const int mrow0 = warp_m * 32 + mt * 16 + r_lo;
                float v0 = fmaxf(acc[mt][nt][0] + bias0, 0.f);
                float v1 = fmaxf(acc[mt][nt][1] + bias1, 0.f);
                float v2 = fmaxf(acc[mt][nt][2] + bias0, 0.f);
                float v3 = fmaxf(acc[mt][nt][3] + bias1, 0.f);
                char* base = smem + 1024 + warp_n * 16384;
                *(__half2*)(base + mrow0 * 128 + ((nt ^ (mrow0 & 7)) << 4) + c_lo * 4) =
                    __floats2half2_rn(v0, v1);
                int mrow1 = mrow0 + 8;
                *(__half2*)(base + mrow1 * 128 + ((nt ^ (mrow1 & 7)) << 4) + c_lo * 4) =
                    __floats2half2_rn(v2, v3);
            }
        }
    }
    #pragma unroll
    for (int mt = 0; mt < 2; ++mt)
        #pragma unroll
        for (int nt = 0; nt < 8; ++nt)
            #pragma unroll
            for (int q = 0; q < 4; ++q) acc[mt][nt][q] = 0.f;
    __syncthreads();

    // ---- Phase 2 ----
    #pragma unroll
    for (int kc2 = 0; kc2 < 4; ++kc2) {
        MBARRIER_WAIT_PARITY(FULLB + (4 + kc2) * 8, 0);
        const uint32_t As2 = TILE + kc2 * 16384;
        const uint32_t Bs2 = W2S  + kc2 * 32768;
        #pragma unroll
        for (int kc = 0; kc < 4; ++kc) {
            uint32_t af[2][4];
            #pragma unroll
            for (int mt = 0; mt < 2; ++mt) {
                int m = warp_m * 32 + mt * 16 + gA_m + r_in;
                int u = kc * 2 + gA_u;
                LDMATRIX_X4(af[mt][0], af[mt][1], af[mt][2], af[mt][3],
                            As2 + m * 128 + ((u ^ (m & 7)) << 4));
            }
            uint32_t bf[8][2];
            #pragma unroll
            for (int nt2 = 0; nt2 < 4; ++nt2) {
                int nn = warp_n * 64 + nt2 * 16 + gB_n + r_in;
                int u  = kc * 2 + gB_u;
                LDMATRIX_X4(bf[2*nt2][0], bf[2*nt2][1], bf[2*nt2+1][0], bf[2*nt2+1][1],
                            Bs2 + nn * 128 + ((u ^ (nn & 7)) << 4));
            }
            #pragma unroll
            for (int mt = 0; mt < 2; ++mt)
                #pragma unroll
                for (int nt = 0; nt < 8; ++nt)
                    mma_f16(acc[mt][nt], af[mt], bf[nt][0], bf[nt][1]);
        }
    }
    __syncthreads();

    // ---- W3 prefetch chunks 0,1 ----
    if (tid == 0) {
        #pragma unroll
        for (int c = 0; c < 2; ++c) {
            MBARRIER_EXPECT_TX(FULLB + (4 + c) * 8, 65536);
            #pragma unroll
            for (int j = 0; j < 4; ++j)
                TMA_LOAD_2D(W2S + c * 65536 + j * 16384, &tmB3,
                            j * 64, c * 128, FULLB + (4 + c) * 8);
        }
    }

    // ---- h2 -> SMEM chunks ----
    {
        const int r_lo = lane >> 2;
        const int c_lo = lane & 3;
        #pragma unroll
        for (int nt = 0; nt < 8; ++nt) {
            const int col = warp_n * 64 + nt * 8 + c_lo * 2;
            const float bias0 = b2[col], bias1 = b2[col + 1];
            #pragma unroll
            for (int mt = 0; mt < 2; ++mt) {
                const int mrow0 = warp_m * 32 + mt * 16 + r_lo;
                float v0 = fmaxf(acc[mt][nt][0] + bias0, 0.f);
                float v1 = fmaxf(acc[mt][nt][1] + bias1, 0.f);
                float v2 = fmaxf(acc[mt][nt][2] + bias0, 0.f);
                float v3 = fmaxf(acc[mt][nt][3] + bias1, 0.f);
                char* base = smem + 1024 + warp_n * 16384;
                *(__half2*)(base + mrow0 * 128 + ((nt ^ (mrow0 & 7)) << 4) + c_lo * 4) =
                    __floats2half2_rn(v0, v1);
                int mrow1 = mrow0 + 8;
                *(__half2*)(base + mrow1 * 128 + ((nt ^ (mrow1 & 7)) << 4) + c_lo * 4) =
                    __floats2half2_rn(v2, v3);
            }
        }
    }
    __syncthreads();

    // ---- Phase 3: 9 n-chunks, Q-sum ----
    float qs = 0.f;
    const int r_lo = lane >> 2;
    const int c_lo = lane & 3;
    for (int c = 0; c < 9; ++c) {
        const int bsel = c & 1;
        MBARRIER_WAIT_PARITY(FULLB + (4 + bsel) * 8, (1 + (c >> 1)) & 1);

        float a3[2][4][4];
        #pragma unroll
        for (int mt = 0; mt < 2; ++mt)
            #pragma unroll
            for (int nt = 0; nt < 4; ++nt)
                #pragma unroll
                for (int q = 0; q < 4; ++q) a3[mt][nt][q] = 0.f;

        const uint32_t Bs3 = W2S + bsel * 65536;
        #pragma unroll
        for (int kk = 0; kk < 4; ++kk) {
            const uint32_t As3 = TILE + kk * 16384;
            const uint32_t Bk3 = Bs3 + kk * 16384;
            #pragma unroll
            for (int kc = 0; kc < 4; ++kc) {
                uint32_t af[2][4];
                #pragma unroll
                for (int mt = 0; mt < 2; ++mt) {
                    int m = warp_m * 32 + mt * 16 + gA_m + r_in;
                    int u = kc * 2 + gA_u;
                    LDMATRIX_X4(af[mt][0], af[mt][1], af[mt][2], af[mt][3],
                                As3 + m * 128 + ((u ^ (m & 7)) << 4));
                }
                uint32_t bf[4][2];
                #pragma unroll
                for (int nt2 = 0; nt2 < 2; ++nt2) {
                    int nn = warp_n * 32 + nt2 * 16 + gB_n + r_in;
                    int u  = kc * 2 + gB_u;
                    LDMATRIX_X4(bf[2*nt2][0], bf[2*nt2][1], bf[2*nt2+1][0], bf[2*nt2+1][1],
                                Bk3 + nn * 128 + ((u ^ (nn & 7)) << 4));
                }
                #pragma unroll
                for (int mt = 0; mt < 2; ++mt)
                    #pragma unroll
                    for (int nt = 0; nt < 4; ++nt)
                        mma_f16(a3[mt][nt], af[mt], bf[nt][0], bf[nt][1]);
            }
        }

        #pragma unroll
        for (int nt = 0; nt < 4; ++nt) {
            const int col = c * 128 + warp_n * 32 + nt * 8 + c_lo * 2;
            const float bias0 = b3[col], bias1 = b3[col + 1];
            #pragma unroll
            for (int mt = 0; mt < 2; ++mt) {
                const int row0 = m0 + warp_m * 32 + mt * 16 + r_lo;
                float v0 = a3[mt][nt][0] + bias0;
                float v1 = a3[mt][nt][1] + bias1;
                float v2 = a3[mt][nt][2] + bias0;
                float v3 = a3[mt][nt][3] + bias1;
                qs += v0 * v0 + v1 * v1 + v2 * v2 + v3 * v3;
                *(__half2*)(dev + (size_t)row0 * OUTFv + col)       = __floats2half2_rn(v0, v1);
                *(__half2*)(dev + (size_t)(row0 + 8) * OUTFv + col) = __floats2half2_rn(v2, v3);
            }
        }
        __syncthreads();
        if (tid == 0 && c + 2 < 9) {
            MBARRIER_EXPECT_TX(FULLB + (4 + bsel) * 8, 65536);
            #pragma unroll
            for (int j = 0; j < 4; ++j)
                TMA_LOAD_2D(W2S + bsel * 65536 + j * 16384, &tmB3,
                            j * 64, (c + 2) * 128, FULLB + (4 + bsel) * 8);
        }
    }

    // ---- Q block reduction ----
    qs = warp_sum(qs);
    if (lane == 0) sred[wid] = qs;
    __syncthreads();
    if (wid == 0) {
        float t = (lane < 16) ? sred[lane] : 0.f;
        t = warp_sum(t);
        if (lane == 0) atomicAdd(Qacc, t);
    }
}

// ---------------------------------------------------------------------------
// Weight transpose to fp16 K-major
// ---------------------------------------------------------------------------
__global__ void transpose_kernel(const float* __restrict__ W, __half* __restrict__ Wt,
                                 int K, int N)
{
    __shared__ float t[32][33];
    int k0 = blockIdx.x * 32, n0 = blockIdx.y * 32;
    int x = threadIdx.x, y0 = threadIdx.y;
    #pragma unroll
    for (int dy = 0; dy < 32; dy += 8) {
        int k = k0 + y0 + dy, n = n0 + x;
        if (k < K && n < N) t[y0 + dy][x] = W[(size_t)k * N + n];
    }
    __syncthreads();
    #pragma unroll
    for (int dy = 0; dy < 32; dy += 8) {
        int n = n0 + y0 + dy, k = k0 + x;
        if (n < N && k < K) Wt[(size_t)n * K + k] = __float2half_rn(t[x][y0 + dy]);
    }
}

// ---------------------------------------------------------------------------
// init / step / finalize
// step: 4608 blocks x 256 threads (small blocks co-resident with fused CTAs).
// Block j covers 256 vec8 items of row-block j/36; publishes g_flag[n][rb].
// ---------------------------------------------------------------------------
__global__ void __launch_bounds__(512)
init_kernel(const float* __restrict__ noisy) {
    int i = blockIdx.x * 512 + threadIdx.x;       // vec8 index, total Bv*72
    if (i < Tv) { g_res[i] = 0.f; g_del[i] = 0.f; g_Q[i] = 0.f; }
    if (i < Tv * NCTA) g_flag[i] = 0;
    int b = i / 72, c8 = (i - b * 72) * 8;
    float4 v0 = make_float4(0.f, 0.f, 0.f, 0.f), v1 = v0;
    if (c8 < 64) {
        v0 = *(const float4*)(noisy + b * 64 + c8);
        v1 = *(const float4*)(noisy + b * 64 + c8 + 4);
    }
    float* frow = g_inp + (size_t)b * INF2;
    *(float4*)(frow + c8)          = v0;
    *(float4*)(frow + c8 + 4)      = v1;
    *(float4*)(frow + Cv + c8)     = v0;
    *(float4*)(frow + Cv + c8 + 4) = v1;
    __half* hrow = g_inph + (size_t)b * INFv;
    uint4 h;
    *(__half2*)&h.x = __floats2half2_rn(v0.x, v0.y);
    *(__half2*)&h.y = __floats2half2_rn(v0.z, v0.w);
    *(__half2*)&h.z = __floats2half2_rn(v1.x, v1.y);
    *(__half2*)&h.w = __floats2half2_rn(v1.z, v1.w);
    *(uint4*)(hrow + c8)        = h;
    *(uint4*)(hrow + Cv + c8)   = h;
    *(uint4*)(hrow + 2*Cv + c8) = h;
    *(uint4*)(hrow + 3*Cv + c8) = h;
}

__global__ void __launch_bounds__(256)
step_kernel(int n) {
    __shared__ float sred[16];
    const int rb    = blockIdx.x / SUBS;              // row-block 0..127
    const int sub   = blockIdx.x - rb * SUBS;         // 0..35
    const int witem = sub * 256 + threadIdx.x;        // 0..9215 within row-block
    const int brow  = rb * 128 + witem / 72;
    const int c8    = (witem % 72) * 8;

    float* frow  = g_inp  + (size_t)brow * INF2;
    __half* hrow = g_inph + (size_t)brow * INFv;
    const __half* orow = g_devh + (size_t)brow * OUTFv;

    float4 x0 = *(float4*)(frow + c8);
    float4 x1 = *(float4*)(frow + c8 + 4);
    float4 p0 = *(float4*)(frow + Cv + c8);
    float4 p1 = *(float4*)(frow + Cv + c8 + 4);
    uint4  yr = *(uint4*)(hrow + 2*Cv + c8);
    uint4  zr = *(uint4*)(hrow + 3*Cv + c8);
    uint4  ur = make_uint4(0,0,0,0), vr = make_uint4(0,0,0,0);
    if (n > 0) {
        ur = *(const uint4*)(orow + c8);
        vr = *(const uint4*)(orow + Cv + c8);
    }

    float al = 0.f;
    if (n > 0) {
        float delta = g_del[n - 1];
        float Q     = 1.5f * g_Q[n - 1] + 1e-12f;
        al = sqrtf(fminf(0.99f * fmaxf(delta, 0.f) / Q, 1.f));
    }
    float nf = (float)n;
    float a  = nf / (nf + 3.f);

    float xs[8] = {x0.x,x0.y,x0.z,x0.w, x1.x,x1.y,x1.z,x1.w};
    float ps[8] = {p0.x,p0.y,p0.z,p0.w, p1.x,p1.y,p1.z,p1.w};
    float ys[8], zs[8], uu[8], vv[8];
    {
        const uint32_t* yw = (const uint32_t*)&yr;
        const uint32_t* zw = (const uint32_t*)&zr;
        const uint32_t* uw = (const uint32_t*)&ur;
        const uint32_t* vw = (const uint32_t*)&vr;
        #pragma unroll
        for (int q = 0; q < 4; ++q) {
            __half2 yh = *(__half2*)&yw[q];
            __half2 zh = *(__half2*)&zw[q];
            __half2 uh = *(__half2*)&uw[q];
            __half2 vh = *(__half2*)&vw[q];
            ys[2*q] = __low2float(yh); ys[2*q+1] = __high2float(yh);
            zs[2*q] = __low2float(zh); zs[2*q+1] = __high2float(zh);
            uu[2*q] = al * __low2float(uh); uu[2*q+1] = al * __high2float(uh);
            vv[2*q] = al * __low2float(vh); vv[2*q+1] = al * __high2float(vh);
        }
    }

    float xn[8], pr[8], yn[8], zn[8];
    float rsum = 0.f, dsum = 0.f;
    #pragma unroll
    for (int j = 0; j < 8; ++j) {
        float ynj = xs[j] + a * (ys[j] - xs[j]) + uu[j];
        float zp  = a * (zs[j] - ps[j]);
        float znj = xs[j] + a * (ps[j] - xs[j]) + zp + uu[j] + vv[j];
        float zm  = znj - ynj;
        float prj = copysignf(fmaxf(fabsf(zm) - 0.1f, 0.f), zm);
        float xnj = xs[j] + (prj - znj) + zp;
        xn[j] = xnj; pr[j] = prj; yn[j] = ynj; zn[j] = znj;
        float r = prj - ynj; rsum += r * r;
        float d = xnj - znj; dsum += d * d;
    }

    *(float4*)(frow + c8)          = make_float4(xn[0], xn[1], xn[2], xn[3]);
    *(float4*)(frow + c8 + 4)      = make_float4(xn[4], xn[5], xn[6], xn[7]);
    *(float4*)(frow + Cv + c8)     = make_float4(pr[0], pr[1], pr[2], pr[3]);
    *(float4*)(frow + Cv + c8 + 4) = make_float4(pr[4], pr[5], pr[6], pr[7]);

    uint4 hx, hp, hy, hz;
    {
        uint32_t* w;
        w = (uint32_t*)&hx;
        #pragma unroll
        for (int q = 0; q < 4; ++q) *(__half2*)&w[q] = __floats2half2_rn(xn[2*q], xn[2*q+1]);
        w = (uint32_t*)&hp;
        #pragma unroll
        for (int q = 0; q < 4; ++q) *(__half2*)&w[q] = __floats2half2_rn(pr[2*q], pr[2*q+1]);
        w = (uint32_t*)&hy;
        #pragma unroll
        for (int q = 0; q < 4; ++q) *(__half2*)&w[q] = __floats2half2_rn(yn[2*q], yn[2*q+1]);
        w = (uint32_t*)&hz;
        #pragma unroll
        for (int q = 0; q < 4; ++q) *(__half2*)&w[q] = __floats2half2_rn(zn[2*q], zn[2*q+1]);
    }
    *(uint4*)(hrow + c8)        = hx;
    *(uint4*)(hrow + Cv + c8)   = hp;
    *(uint4*)(hrow + 2*Cv + c8) = hy;
    *(uint4*)(hrow + 3*Cv + c8) = hz;

    rsum = warp_sum(rsum); dsum = warp_sum(dsum);
    int lane = threadIdx.x & 31, wid = threadIdx.x >> 5;   // 8 warps
    if (lane == 0) { sred[wid] = rsum; sred[8 + wid] = dsum; }
    __syncthreads();
    if (wid == 0) {
        float rr = (lane < 8) ? sred[lane] : 0.f;
        rr = warp_sum(rr);
        if (lane == 0) atomicAdd(&g_res[n], rr);
    } else if (wid == 1) {
        float dd = (lane < 8) ? sred[8 + lane] : 0.f;
        dd = warp_sum(dd);
        if (lane == 0) atomicAdd(&g_del[n], dd);
    }
    __syncthreads();
    if (threadIdx.x == 0) {
        __threadfence();
        atomicAdd(&g_flag[n * NCTA + rb], 1);
    }
}

__global__ void __launch_bounds__(512)
finalize_kernel(float* __restrict__ out) {
    int i = blockIdx.x * 512 + threadIdx.x;
    int b = i / 72, c8 = (i - b * 72) * 8;
    const float* src = g_inp + (size_t)b * INF2 + Cv + c8;
    float4 v0 = *(const float4*)(src);
    float4 v1 = *(const float4*)(src + 4);
    *(float4*)(out + (size_t)b * Cv + c8)     = v0;
    *(float4*)(out + (size_t)b * Cv + c8 + 4) = v1;
    if (i < Tv) out[(size_t)Bv * Cv + i] = sqrtf(g_res[i] + 1e-12f);
}

// ---------------------------------------------------------------------------
// Host side
// ---------------------------------------------------------------------------
typedef CUresult (*EncodeFn)(CUtensorMap*, CUtensorMapDataType, cuuint32_t, void*,
                             const cuuint64_t*, const cuuint64_t*, const cuuint32_t*,
                             const cuuint32_t*, CUtensorMapInterleave, CUtensorMapSwizzle,
                             CUtensorMapL2promotion, CUtensorMapFloatOOBfill);

static void make_map_h(EncodeFn enc, CUtensorMap* tm, void* base, int Kdim, int rows) {
    cuuint64_t dims[2]    = {(cuuint64_t)Kdim, (cuuint64_t)rows};
    cuuint64_t strides[1] = {(cuuint64_t)Kdim * 2};
    cuuint32_t box[2]     = {64u, 128u};
    cuuint32_t es[2]      = {1u, 1u};
    enc(tm, CU_TENSOR_MAP_DATA_TYPE_FLOAT16, 2, base, dims, strides, box, es,
        CU_TENSOR_MAP_INTERLEAVE_NONE, CU_TENSOR_MAP_SWIZZLE_128B,
        CU_TENSOR_MAP_L2_PROMOTION_L2_128B, CU_TENSOR_MAP_FLOAT_OOB_FILL_NONE);
}

extern "C" void kernel_launch(void* const* d_in, const int* in_sizes, int n_in,
                              void* d_out, int out_size) {
    const float* noisy = (const float*)d_in[0];
    const float* W1 = (const float*)d_in[1];
    const float* b1 = (const float*)d_in[2];
    const float* W2 = (const float*)d_in[3];
    const float* b2 = (const float*)d_in[4];
    const float* W3 = (const float*)d_in[5];
    const float* b3 = (const float*)d_in[6];
    float* out = (float*)d_out;

    __half *inph, *devh, *W1h, *W2h, *W3h;
    float *Qarr;
    cudaGetSymbolAddress((void**)&inph, g_inph);
    cudaGetSymbolAddress((void**)&devh, g_devh);
    cudaGetSymbolAddress((void**)&Qarr, g_Q);
    cudaGetSymbolAddress((void**)&W1h,  g_W1h);
    cudaGetSymbolAddress((void**)&W2h,  g_W2h);
    cudaGetSymbolAddress((void**)&W3h,  g_W3h);

    static EncodeFn enc = nullptr;
    static cudaStream_t s2 = nullptr;
    static cudaEvent_t forkEv = nullptr;
    static cudaEvent_t fEv[Tv];
    if (!enc) {
        void* p = nullptr;
        cudaDriverEntryPointQueryResult st;
        cudaGetDriverEntryPoint("cuTensorMapEncodeTiled", &p, cudaEnableDefault, &st);
        enc = (EncodeFn)p;
        cudaStreamCreateWithFlags(&s2, cudaStreamNonBlocking);
        cudaEventCreateWithFlags(&forkEv, cudaEventDisableTiming);
        for (int i = 0; i < Tv; ++i)
            cudaEventCreateWithFlags(&fEv[i], cudaEventDisableTiming);
    }

    CUtensorMap tA1, tB1, tB2, tB3;
    make_map_h(enc, &tA1, inph, INFv, Bv);
    make_map_h(enc, &tB1, W1h,  INFv, HIDv);
    make_map_h(enc, &tB2, W2h,  HIDv, HIDv);
    make_map_h(enc, &tB3, W3h,  HIDv, OUTFv);

    const int SMEM_SZ = 1024 + 4 * (3 * 16384);   // 197632
    static bool attr_set = false;
    if (!attr_set) {
        cudaFuncSetAttribute(fused123, cudaFuncAttributeMaxDynamicSharedMemorySize, SMEM_SZ);
        attr_set = true;
    }

    dim3 tb(32, 8);
    transpose_kernel<<<dim3(INFv/32, HIDv/32),  tb>>>(W1, W1h, INFv, HIDv);
    transpose_kernel<<<dim3(HIDv/32, HIDv/32),  tb>>>(W2, W2h, HIDv, HIDv);
    transpose_kernel<<<dim3(HIDv/32, OUTFv/32), tb>>>(W3, W3h, HIDv, OUTFv);

    const int VBLK8 = (Bv * 72) / 512;   // 2304
    init_kernel<<<VBLK8, 512>>>(noisy);

    // fork second stream off the origin stream (flags zeroed by init)
    cudaEventRecord(forkEv, 0);
    cudaStreamWaitEvent(s2, forkEv, 0);

    for (int n = 0; n < Tv; ++n) {
        if (n > 0) cudaStreamWaitEvent(0, fEv[n - 1], 0);    // dev(n-1), Q(n-1) ready
        step_kernel<<<NCTA * SUBS, 256>>>(n);                // origin stream, small blocks
        fused123<<<NCTA, 512, SMEM_SZ, s2>>>(tA1, tB1, tB2, tB3, b1, b2, b3,
                                             devh, Qarr + n, n);  // overlaps step(n)
        cudaEventRecord(fEv[n], s2);
    }
    cudaStreamWaitEvent(0, fEv[Tv - 1], 0);   // join
    finalize_kernel<<<VBLK8, 512>>>(out);
}

// round 15
// speedup vs baseline: 1.5146x; 1.0251x over previous
#include <cuda_runtime.h>
#include <cuda.h>
#include <cuda_fp16.h>
#include <math.h>
#include <stdint.h>

// Problem constants (fixed by setup_inputs)
#define Bv    16384
#define Cv    576          // N_CH*SIZE*SIZE
#define INFv  2304         // 4*Cv
#define HIDv  256
#define OUTFv 1152         // 2*Cv
#define Tv    20
#define INF2  1152         // fp32 state slices: [x | p]
#define NCTA  128          // fused123 CTAs (row-blocks)
#define SUBS  36           // step sub-blocks per row-block (256 thr each)

// Persistent scratch (device globals; no allocations allowed)
__device__ __align__(1024) float  g_inp [(size_t)Bv * INF2];   // fp32 [x | p]
__device__ __align__(1024) __half g_inph[(size_t)Bv * INFv];   // fp16 mirror [x|p|y|z]
__device__ __align__(1024) __half g_devh[(size_t)Bv * OUTFv];  // [u_raw | v_raw] fp16
__device__ __align__(1024) __half g_W1h[(size_t)HIDv  * INFv]; // K-major [256,2304]
__device__ __align__(1024) __half g_W2h[(size_t)HIDv  * HIDv];
__device__ __align__(1024) __half g_W3h[(size_t)OUTFv * HIDv];
__device__ float g_res[Tv];
__device__ float g_del[Tv];
__device__ float g_Q  [Tv];
__device__ int   g_flag[Tv * NCTA];   // per-(iter,row-block) step completion

// ---------------------------------------------------------------------------
// PTX helpers
// ---------------------------------------------------------------------------
__device__ __forceinline__ uint32_t smem_to_u32(const void* p) {
    uint32_t a;
    asm("{ .reg .u64 t; cvta.to.shared.u64 t, %1; cvt.u32.u64 %0, t; }"
        : "=r"(a) : "l"(p));
    return a;
}

#define MBARRIER_INIT(addr, cnt) \
    asm volatile("mbarrier.init.shared.b64 [%0], %1;" :: "r"((uint32_t)(addr)), "r"((uint32_t)(cnt)) : "memory")
#define MBARRIER_EXPECT_TX(addr, bytes) \
    asm volatile("mbarrier.arrive.expect_tx.shared.b64 _, [%0], %1;" :: "r"((uint32_t)(addr)), "r"((uint32_t)(bytes)) : "memory")

#define MBARRIER_WAIT_PARITY(mbar, par) do { \
    uint32_t _m = (uint32_t)(mbar), _p = (uint32_t)(par), _d; \
    asm volatile("{\n\t.reg .pred p;\n\t" \
        "mbarrier.try_wait.parity.acquire.cta.shared::cta.b64 p, [%1], %2;\n\t" \
        "selp.b32 %0, 1, 0, p;\n\t}" : "=r"(_d) : "r"(_m), "r"(_p) : "memory"); \
    if (!_d) { \
        asm volatile("{\n\t.reg .pred P1;\n\t" \
            "W_%=:\n\t" \
            "mbarrier.try_wait.parity.acquire.cta.shared::cta.b64 P1, [%0], %1, 0x989680;\n\t" \
            "@P1 bra.uni D_%=;\n\tbra.uni W_%=;\n\tD_%=:\n\t}" \
            :: "r"(_m), "r"(_p) : "memory"); \
    } \
} while(0)

#define TMA_LOAD_2D(smem_addr, map_ptr, cx, cy, mbar) \
    asm volatile("cp.async.bulk.tensor.2d.shared::cta.global.tile.mbarrier::complete_tx::bytes " \
        "[%0], [%1, {%2, %3}], [%4];" \
        :: "r"((uint32_t)(smem_addr)), "l"(map_ptr), "r"((int32_t)(cx)), "r"((int32_t)(cy)), \
           "r"((uint32_t)(mbar)) : "memory")

#define FENCE_PROXY_ASYNC() asm volatile("fence.proxy.async;" ::: "memory")

#define LDMATRIX_X4(r0, r1, r2, r3, addr) \
    asm volatile("ldmatrix.sync.aligned.m8n8.x4.shared.b16 {%0,%1,%2,%3}, [%4];" \
        : "=r"(r0), "=r"(r1), "=r"(r2), "=r"(r3) : "r"(addr))

__device__ __forceinline__ void mma_f16(float* d, const uint32_t* a,
                                        uint32_t b0, uint32_t b1) {
    asm volatile(
        "mma.sync.aligned.m16n8k16.row.col.f32.f16.f16.f32 "
        "{%0,%1,%2,%3}, {%4,%5,%6,%7}, {%8,%9}, {%0,%1,%2,%3};"
        : "+f"(d[0]), "+f"(d[1]), "+f"(d[2]), "+f"(d[3])
        : "r"(a[0]), "r"(a[1]), "r"(a[2]), "r"(a[3]), "r"(b0), "r"(b1));
}

__device__ __forceinline__ float warp_sum(float v) {
    #pragma unroll
    for (int o = 16; o > 0; o >>= 1) v += __shfl_down_sync(0xffffffffu, v, o);
    return v;
}

__device__ __forceinline__ int ld_volatile_i32(const int* p) {
    int v;
    asm volatile("ld.volatile.global.s32 %0, [%1];" : "=r"(v) : "l"(p));
    return v;
}

// ---------------------------------------------------------------------------
// FUSED GEMM1+GEMM2+GEMM3 + per-row-block flag spin at entry.
// __maxnreg__(112): 512*112 = 57344 regs -> 8192 free so one 256-thread
// step block can CO-RESIDE on the same SM. (SMEM already caps at 1 CTA/SM,
// so no __launch_bounds__ needed — the two qualifiers are mutually exclusive.)
// ---------------------------------------------------------------------------
__global__ void __maxnreg__(112)
fused123(const __grid_constant__ CUtensorMap tmA,
         const __grid_constant__ CUtensorMap tmB1,
         const __grid_constant__ CUtensorMap tmB2,
         const __grid_constant__ CUtensorMap tmB3,
         const float* __restrict__ b1, const float* __restrict__ b2,
         const float* __restrict__ b3,
         __half* __restrict__ dev, float* __restrict__ Qacc, int n)
{
    constexpr int STAGES  = 4;
    constexpr int A_BYTES = 128 * 64 * 2;
    constexpr int B_BYTES = 256 * 64 * 2;
    constexpr int STAGE_B = A_BYTES + B_BYTES;
    constexpr int NITER   = INFv / 64;        // 36

    extern __shared__ char smem[];
    const uint32_t sb = smem_to_u32(smem);
    const int tid  = threadIdx.x;
    const int wid  = tid >> 5;
    const int lane = tid & 31;
    const int warp_m = wid >> 2;
    const int warp_n = wid & 3;
    const int m0 = blockIdx.x * 128;

    const uint32_t FULLB = sb;                // 8 mbarriers
    float* sred = (float*)(smem + 128);
    const uint32_t TILE  = sb + 1024;
    const uint32_t W2S   = TILE + 65536;

    // ---- wait for this row-block's step to finish (SUBS sub-blocks) ----
    if (tid == 0) {
        while (ld_volatile_i32(&g_flag[n * NCTA + blockIdx.x]) < SUBS) { }
        __threadfence();
        #pragma unroll
        for (int s = 0; s < 8; ++s) MBARRIER_INIT(FULLB + s * 8, 1);
        FENCE_PROXY_ASYNC();
    }
    __syncthreads();

    if (tid == 0) {
        #pragma unroll
        for (int s = 0; s < STAGES - 1; ++s) {
            MBARRIER_EXPECT_TX(FULLB + s * 8, STAGE_B);
            TMA_LOAD_2D(TILE + s * STAGE_B, &tmA, s * 64, m0, FULLB + s * 8);
            TMA_LOAD_2D(TILE + s * STAGE_B + A_BYTES,         &tmB1, s * 64, 0,   FULLB + s * 8);
            TMA_LOAD_2D(TILE + s * STAGE_B + A_BYTES + 16384, &tmB1, s * 64, 128, FULLB + s * 8);
        }
    }

    float acc[2][8][4];
    #pragma unroll
    for (int mt = 0; mt < 2; ++mt)
        #pragma unroll
        for (int nt = 0; nt < 8; ++nt)
            #pragma unroll
            for (int q = 0; q < 4; ++q) acc[mt][nt][q] = 0.f;

    const int r_in = lane & 7;
    const int gA_m = ((lane >> 3) & 1) * 8;
    const int gA_u = (lane >> 4);
    const int gB_n = (lane >> 4) * 8;
    const int gB_u = ((lane >> 3) & 1);

    // ---- Phase 1 ----
    for (int it = 0; it < NITER; ++it) {
        const int s = it % STAGES;
        MBARRIER_WAIT_PARITY(FULLB + s * 8, (it / STAGES) & 1);

        if (tid == 0) {
            int nx = it + STAGES - 1;
            if (nx < NITER) {
                int sx = nx % STAGES;
                MBARRIER_EXPECT_TX(FULLB + sx * 8, STAGE_B);
                TMA_LOAD_2D(TILE + sx * STAGE_B, &tmA, nx * 64, m0, FULLB + sx * 8);
                TMA_LOAD_2D(TILE + sx * STAGE_B + A_BYTES,         &tmB1, nx * 64, 0,   FULLB + sx * 8);
                TMA_LOAD_2D(TILE + sx * STAGE_B + A_BYTES + 16384, &tmB1, nx * 64, 128, FULLB + sx * 8);
            }
        }

        const uint32_t As = TILE + s * STAGE_B;
        const uint32_t Bs = As + A_BYTES;

        #pragma unroll
        for (int kc = 0; kc < 4; ++kc) {
            uint32_t af[2][4];
            #pragma unroll
            for (int mt = 0; mt < 2; ++mt) {
                int m = warp_m * 32 + mt * 16 + gA_m + r_in;
                int u = kc * 2 + gA_u;
                LDMATRIX_X4(af[mt][0], af[mt][1], af[mt][2], af[mt][3],
                            As + m * 128 + ((u ^ (m & 7)) << 4));
            }
            uint32_t bf[8][2];
            #pragma unroll
            for (int nt2 = 0; nt2 < 4; ++nt2) {
                int nn = warp_n * 64 + nt2 * 16 + gB_n + r_in;
                int u  = kc * 2 + gB_u;
                LDMATRIX_X4(bf[2*nt2][0], bf[2*nt2][1], bf[2*nt2+1][0], bf[2*nt2+1][1],
                            Bs + nn * 128 + ((u ^ (nn & 7)) << 4));
            }
            #pragma unroll
            for (int mt = 0; mt < 2; ++mt)
                #pragma unroll
                for (int nt = 0; nt < 8; ++nt)
                    mma_f16(acc[mt][nt], af[mt], bf[nt][0], bf[nt][1]);
        }
        __syncthreads();
    }

    // ---- W2 prefetch ----
    if (tid == 0) {
        #pragma unroll
        for (int kc2 = 0; kc2 < 4; ++kc2) {
            MBARRIER_EXPECT_TX(FULLB + (4 + kc2) * 8, 32768);
            TMA_LOAD_2D(W2S + kc2 * 32768,         &tmB2, kc2 * 64, 0,   FULLB + (4 + kc2) * 8);
            TMA_LOAD_2D(W2S + kc2 * 32768 + 16384, &tmB2, kc2 * 64, 128, FULLB + (4 + kc2) * 8);
        }
    }

    // ---- h1 -> SMEM chunks ----
    {
        const int r_lo = lane >> 2;
        const int c_lo = lane & 3;
        #pragma unroll
        for (int nt = 0; nt < 8; ++nt) {
            const int col = warp_n * 64 + nt * 8 + c_lo * 2;
            const float bias0 = b1[col], bias1 = b1[col + 1];
            #pragma unroll
            for (int mt = 0; mt < 2; ++mt) {
                const int mrow0 = warp_m * 32 + mt * 16 + r_lo;
                float v0 = fmaxf(acc[mt][nt][0] + bias0, 0.f);
                float v1 = fmaxf(acc[mt][nt][1] + bias1, 0.f);
                float v2 = fmaxf(acc[mt][nt][2] + bias0, 0.f);
                float v3 = fmaxf(acc[mt][nt][3] + bias1, 0.f);
                char* base = smem + 1024 + warp_n * 16384;
                *(__half2*)(base + mrow0 * 128 + ((nt ^ (mrow0 & 7)) << 4) + c_lo * 4) =
                    __floats2half2_rn(v0, v1);
                int mrow1 = mrow0 + 8;
                *(__half2*)(base + mrow1 * 128 + ((nt ^ (mrow1 & 7)) << 4) + c_lo * 4) =
                    __floats2half2_rn(v2, v3);
            }
        }
    }
    #pragma unroll
    for (int mt = 0; mt < 2; ++mt)
        #pragma unroll
        for (int nt = 0; nt < 8; ++nt)
            #pragma unroll
            for (int q = 0; q < 4; ++q) acc[mt][nt][q] = 0.f;
    __syncthreads();

    // ---- Phase 2 ----
    #pragma unroll
    for (int kc2 = 0; kc2 < 4; ++kc2) {
        MBARRIER_WAIT_PARITY(FULLB + (4 + kc2) * 8, 0);
        const uint32_t As2 = TILE + kc2 * 16384;
        const uint32_t Bs2 = W2S  + kc2 * 32768;
        #pragma unroll
        for (int kc = 0; kc < 4; ++kc) {
            uint32_t af[2][4];
            #pragma unroll
            for (int mt = 0; mt < 2; ++mt) {
                int m = warp_m * 32 + mt * 16 + gA_m + r_in;
                int u = kc * 2 + gA_u;
                LDMATRIX_X4(af[mt][0], af[mt][1], af[mt][2], af[mt][3],
                            As2 + m * 128 + ((u ^ (m & 7)) << 4));
            }
            uint32_t bf[8][2];
            #pragma unroll
            for (int nt2 = 0; nt2 < 4; ++nt2) {
                int nn = warp_n * 64 + nt2 * 16 + gB_n + r_in;
                int u  = kc * 2 + gB_u;
                LDMATRIX_X4(bf[2*nt2][0], bf[2*nt2][1], bf[2*nt2+1][0], bf[2*nt2+1][1],
                            Bs2 + nn * 128 + ((u ^ (nn & 7)) << 4));
            }
            #pragma unroll
            for (int mt = 0; mt < 2; ++mt)
                #pragma unroll
                for (int nt = 0; nt < 8; ++nt)
                    mma_f16(acc[mt][nt], af[mt], bf[nt][0], bf[nt][1]);
        }
    }
    __syncthreads();

    // ---- W3 prefetch chunks 0,1 ----
    if (tid == 0) {
        #pragma unroll
        for (int c = 0; c < 2; ++c) {
            MBARRIER_EXPECT_TX(FULLB + (4 + c) * 8, 65536);
            #pragma unroll
            for (int j = 0; j < 4; ++j)
                TMA_LOAD_2D(W2S + c * 65536 + j * 16384, &tmB3,
                            j * 64, c * 128, FULLB + (4 + c) * 8);
        }
    }

    // ---- h2 -> SMEM chunks ----
    {
        const int r_lo = lane >> 2;
        const int c_lo = lane & 3;
        #pragma unroll
        for (int nt = 0; nt < 8; ++nt) {
            const int col = warp_n * 64 + nt * 8 + c_lo * 2;
            const float bias0 = b2[col], bias1 = b2[col + 1];
            #pragma unroll
            for (int mt = 0; mt < 2; ++mt) {
                const int mrow0 = warp_m * 32 + mt * 16 + r_lo;
                float v0 = fmaxf(acc[mt][nt][0] + bias0, 0.f);
                float v1 = fmaxf(acc[mt][nt][1] + bias1, 0.f);
                float v2 = fmaxf(acc[mt][nt][2] + bias0, 0.f);
                float v3 = fmaxf(acc[mt][nt][3] + bias1, 0.f);
                char* base = smem + 1024 + warp_n * 16384;
                *(__half2*)(base + mrow0 * 128 + ((nt ^ (mrow0 & 7)) << 4) + c_lo * 4) =
                    __floats2half2_rn(v0, v1);
                int mrow1 = mrow0 + 8;
                *(__half2*)(base + mrow1 * 128 + ((nt ^ (mrow1 & 7)) << 4) + c_lo * 4) =
                    __floats2half2_rn(v2, v3);
            }
        }
    }
    __syncthreads();

    // ---- Phase 3: 9 n-chunks, Q-sum ----
    float qs = 0.f;
    const int r_lo = lane >> 2;
    const int c_lo = lane & 3;
    for (int c = 0; c < 9; ++c) {
        const int bsel = c & 1;
        MBARRIER_WAIT_PARITY(FULLB + (4 + bsel) * 8, (1 + (c >> 1)) & 1);

        float a3[2][4][4];
        #pragma unroll
        for (int mt = 0; mt < 2; ++mt)
            #pragma unroll
            for (int nt = 0; nt < 4; ++nt)
                #pragma unroll
                for (int q = 0; q < 4; ++q) a3[mt][nt][q] = 0.f;

        const uint32_t Bs3 = W2S + bsel * 65536;
        #pragma unroll
        for (int kk = 0; kk < 4; ++kk) {
            const uint32_t As3 = TILE + kk * 16384;
            const uint32_t Bk3 = Bs3 + kk * 16384;
            #pragma unroll
            for (int kc = 0; kc < 4; ++kc) {
                uint32_t af[2][4];
                #pragma unroll
                for (int mt = 0; mt < 2; ++mt) {
                    int m = warp_m * 32 + mt * 16 + gA_m + r_in;
                    int u = kc * 2 + gA_u;
                    LDMATRIX_X4(af[mt][0], af[mt][1], af[mt][2], af[mt][3],
                                As3 + m * 128 + ((u ^ (m & 7)) << 4));
                }
                uint32_t bf[4][2];
                #pragma unroll
                for (int nt2 = 0; nt2 < 2; ++nt2) {
                    int nn = warp_n * 32 + nt2 * 16 + gB_n + r_in;
                    int u  = kc * 2 + gB_u;
                    LDMATRIX_X4(bf[2*nt2][0], bf[2*nt2][1], bf[2*nt2+1][0], bf[2*nt2+1][1],
                                Bk3 + nn * 128 + ((u ^ (nn & 7)) << 4));
                }
                #pragma unroll
                for (int mt = 0; mt < 2; ++mt)
                    #pragma unroll
                    for (int nt = 0; nt < 4; ++nt)
                        mma_f16(a3[mt][nt], af[mt], bf[nt][0], bf[nt][1]);
            }
        }

        #pragma unroll
        for (int nt = 0; nt < 4; ++nt) {
            const int col = c * 128 + warp_n * 32 + nt * 8 + c_lo * 2;
            const float bias0 = b3[col], bias1 = b3[col + 1];
            #pragma unroll
            for (int mt = 0; mt < 2; ++mt) {
                const int row0 = m0 + warp_m * 32 + mt * 16 + r_lo;
                float v0 = a3[mt][nt][0] + bias0;
                float v1 = a3[mt][nt][1] + bias1;
                float v2 = a3[mt][nt][2] + bias0;
                float v3 = a3[mt][nt][3] + bias1;
                qs += v0 * v0 + v1 * v1 + v2 * v2 + v3 * v3;
                *(__half2*)(dev + (size_t)row0 * OUTFv + col)       = __floats2half2_rn(v0, v1);
                *(__half2*)(dev + (size_t)(row0 + 8) * OUTFv + col) = __floats2half2_rn(v2, v3);
            }
        }
        __syncthreads();
        if (tid == 0 && c + 2 < 9) {
            MBARRIER_EXPECT_TX(FULLB + (4 + bsel) * 8, 65536);
            #pragma unroll
            for (int j = 0; j < 4; ++j)
                TMA_LOAD_2D(W2S + bsel * 65536 + j * 16384, &tmB3,
                            j * 64, (c + 2) * 128, FULLB + (4 + bsel) * 8);
        }
    }

    // ---- Q block reduction ----
    qs = warp_sum(qs);
    if (lane == 0) sred[wid] = qs;
    __syncthreads();
    if (wid == 0) {
        float t = (lane < 16) ? sred[lane] : 0.f;
        t = warp_sum(t);
        if (lane == 0) atomicAdd(Qacc, t);
    }
}

// ---------------------------------------------------------------------------
// Weight transpose to fp16 K-major
// ---------------------------------------------------------------------------
__global__ void transpose_kernel(const float* __restrict__ W, __half* __restrict__ Wt,
                                 int K, int N)
{
    __shared__ float t[32][33];
    int k0 = blockIdx.x * 32, n0 = blockIdx.y * 32;
    int x = threadIdx.x, y0 = threadIdx.y;
    #pragma unroll
    for (int dy = 0; dy < 32; dy += 8) {
        int k = k0 + y0 + dy, n = n0 + x;
        if (k < K && n < N) t[y0 + dy][x] = W[(size_t)k * N + n];
    }
    __syncthreads();
    #pragma unroll
    for (int dy = 0; dy < 32; dy += 8) {
        int n = n0 + y0 + dy, k = k0 + x;
        if (n < N && k < K) Wt[(size_t)n * K + k] = __float2half_rn(t[x][y0 + dy]);
    }
}

// ---------------------------------------------------------------------------
// init / step / finalize
// ---------------------------------------------------------------------------
__global__ void __launch_bounds__(512)
init_kernel(const float* __restrict__ noisy) {
    int i = blockIdx.x * 512 + threadIdx.x;       // vec8 index, total Bv*72
    if (i < Tv) { g_res[i] = 0.f; g_del[i] = 0.f; g_Q[i] = 0.f; }
    if (i < Tv * NCTA) g_flag[i] = 0;
    int b = i / 72, c8 = (i - b * 72) * 8;
    float4 v0 = make_float4(0.f, 0.f, 0.f, 0.f), v1 = v0;
    if (c8 < 64) {
        v0 = *(const float4*)(noisy + b * 64 + c8);
        v1 = *(const float4*)(noisy + b * 64 + c8 + 4);
    }
    float* frow = g_inp + (size_t)b * INF2;
    *(float4*)(frow + c8)          = v0;
    *(float4*)(frow + c8 + 4)      = v1;
    *(float4*)(frow + Cv + c8)     = v0;
    *(float4*)(frow + Cv + c8 + 4) = v1;
    __half* hrow = g_inph + (size_t)b * INFv;
    uint4 h;
    *(__half2*)&h.x = __floats2half2_rn(v0.x, v0.y);
    *(__half2*)&h.y = __floats2half2_rn(v0.z, v0.w);
    *(__half2*)&h.z = __floats2half2_rn(v1.x, v1.y);
    *(__half2*)&h.w = __floats2half2_rn(v1.z, v1.w);
    *(uint4*)(hrow + c8)        = h;
    *(uint4*)(hrow + Cv + c8)   = h;
    *(uint4*)(hrow + 2*Cv + c8) = h;
    *(uint4*)(hrow + 3*Cv + c8) = h;
}

__global__ void __launch_bounds__(256)
step_kernel(int n) {
    __shared__ float sred[16];
    const int rb    = blockIdx.x / SUBS;              // row-block 0..127
    const int sub   = blockIdx.x - rb * SUBS;         // 0..35
    const int witem = sub * 256 + threadIdx.x;        // 0..9215 within row-block
    const int brow  = rb * 128 + witem / 72;
    const int c8    = (witem % 72) * 8;

    float* frow  = g_inp  + (size_t)brow * INF2;
    __half* hrow = g_inph + (size_t)brow * INFv;
    const __half* orow = g_devh + (size_t)brow * OUTFv;

    float4 x0 = *(float4*)(frow + c8);
    float4 x1 = *(float4*)(frow + c8 + 4);
    float4 p0 = *(float4*)(frow + Cv + c8);
    float4 p1 = *(float4*)(frow + Cv + c8 + 4);
    uint4  yr = *(uint4*)(hrow + 2*Cv + c8);
    uint4  zr = *(uint4*)(hrow + 3*Cv + c8);
    uint4  ur = make_uint4(0,0,0,0), vr = make_uint4(0,0,0,0);
    if (n > 0) {
        ur = *(const uint4*)(orow + c8);
        vr = *(const uint4*)(orow + Cv + c8);
    }

    float al = 0.f;
    if (n > 0) {
        float delta = g_del[n - 1];
        float Q     = 1.5f * g_Q[n - 1] + 1e-12f;
        al = sqrtf(fminf(0.99f * fmaxf(delta, 0.f) / Q, 1.f));
    }
    float nf = (float)n;
    float a  = nf / (nf + 3.f);

    float xs[8] = {x0.x,x0.y,x0.z,x0.w, x1.x,x1.y,x1.z,x1.w};
    float ps[8] = {p0.x,p0.y,p0.z,p0.w, p1.x,p1.y,p1.z,p1.w};
    float ys[8], zs[8], uu[8], vv[8];
    {
        const uint32_t* yw = (const uint32_t*)&yr;
        const uint32_t* zw = (const uint32_t*)&zr;
        const uint32_t* uw = (const uint32_t*)&ur;
        const uint32_t* vw = (const uint32_t*)&vr;
        #pragma unroll
        for (int q = 0; q < 4; ++q) {
            __half2 yh = *(__half2*)&yw[q];
            __half2 zh = *(__half2*)&zw[q];
            __half2 uh = *(__half2*)&uw[q];
            __half2 vh = *(__half2*)&vw[q];
            ys[2*q] = __low2float(yh); ys[2*q+1] = __high2float(yh);
            zs[2*q] = __low2float(zh); zs[2*q+1] = __high2float(zh);
            uu[2*q] = al * __low2float(uh); uu[2*q+1] = al * __high2float(uh);
            vv[2*q] = al * __low2float(vh); vv[2*q+1] = al * __high2float(vh);
        }
    }

    float xn[8], pr[8], yn[8], zn[8];
    float rsum = 0.f, dsum = 0.f;
    #pragma unroll
    for (int j = 0; j < 8; ++j) {
        float ynj = xs[j] + a * (ys[j] - xs[j]) + uu[j];
        float zp  = a * (zs[j] - ps[j]);
        float znj = xs[j] + a * (ps[j] - xs[j]) + zp + uu[j] + vv[j];
        float zm  = znj - ynj;
        float prj = copysignf(fmaxf(fabsf(zm) - 0.1f, 0.f), zm);
        float xnj = xs[j] + (prj - znj) + zp;
        xn[j] = xnj; pr[j] = prj; yn[j] = ynj; zn[j] = znj;
        float r = prj - ynj; rsum += r * r;
        float d = xnj - znj; dsum += d * d;
    }

    *(float4*)(frow + c8)          = make_float4(xn[0], xn[1], xn[2], xn[3]);
    *(float4*)(frow + c8 + 4)      = make_float4(xn[4], xn[5], xn[6], xn[7]);
    *(float4*)(frow + Cv + c8)     = make_float4(pr[0], pr[1], pr[2], pr[3]);
    *(float4*)(frow + Cv + c8 + 4) = make_float4(pr[4], pr[5], pr[6], pr[7]);

    uint4 hx, hp, hy, hz;
    {
        uint32_t* w;
        w = (uint32_t*)&hx;
        #pragma unroll
        for (int q = 0; q < 4; ++q) *(__half2*)&w[q] = __floats2half2_rn(xn[2*q], xn[2*q+1]);
        w = (uint32_t*)&hp;
        #pragma unroll
        for (int q = 0; q < 4; ++q) *(__half2*)&w[q] = __floats2half2_rn(pr[2*q], pr[2*q+1]);
        w = (uint32_t*)&hy;
        #pragma unroll
        for (int q = 0; q < 4; ++q) *(__half2*)&w[q] = __floats2half2_rn(yn[2*q], yn[2*q+1]);
        w = (uint32_t*)&hz;
        #pragma unroll
        for (int q = 0; q < 4; ++q) *(__half2*)&w[q] = __floats2half2_rn(zn[2*q], zn[2*q+1]);
    }
    *(uint4*)(hrow + c8)        = hx;
    *(uint4*)(hrow + Cv + c8)   = hp;
    *(uint4*)(hrow + 2*Cv + c8) = hy;
    *(uint4*)(hrow + 3*Cv + c8) = hz;

    rsum = warp_sum(rsum); dsum = warp_sum(dsum);
    int lane = threadIdx.x & 31, wid = threadIdx.x >> 5;   // 8 warps
    if (lane == 0) { sred[wid] = rsum; sred[8 + wid] = dsum; }
    __syncthreads();
    if (wid == 0) {
        float rr = (lane < 8) ? sred[lane] : 0.f;
        rr = warp_sum(rr);
        if (lane == 0) atomicAdd(&g_res[n], rr);
    } else if (wid == 1) {
        float dd = (lane < 8) ? sred[8 + lane] : 0.f;
        dd = warp_sum(dd);
        if (lane == 0) atomicAdd(&g_del[n], dd);
    }
    __syncthreads();
    if (threadIdx.x == 0) {
        __threadfence();
        atomicAdd(&g_flag[n * NCTA + rb], 1);
    }
}

__global__ void __launch_bounds__(512)
finalize_kernel(float* __restrict__ out) {
    int i = blockIdx.x * 512 + threadIdx.x;
    int b = i / 72, c8 = (i - b * 72) * 8;
    const float* src = g_inp + (size_t)b * INF2 + Cv + c8;
    float4 v0 = *(const float4*)(src);
    float4 v1 = *(const float4*)(src + 4);
    *(float4*)(out + (size_t)b * Cv + c8)     = v0;
    *(float4*)(out + (size_t)b * Cv + c8 + 4) = v1;
    if (i < Tv) out[(size_t)Bv * Cv + i] = sqrtf(g_res[i] + 1e-12f);
}

// ---------------------------------------------------------------------------
// Host side
// ---------------------------------------------------------------------------
typedef CUresult (*EncodeFn)(CUtensorMap*, CUtensorMapDataType, cuuint32_t, void*,
                             const cuuint64_t*, const cuuint64_t*, const cuuint32_t*,
                             const cuuint32_t*, CUtensorMapInterleave, CUtensorMapSwizzle,
                             CUtensorMapL2promotion, CUtensorMapFloatOOBfill);

static void make_map_h(EncodeFn enc, CUtensorMap* tm, void* base, int Kdim, int rows) {
    cuuint64_t dims[2]    = {(cuuint64_t)Kdim, (cuuint64_t)rows};
    cuuint64_t strides[1] = {(cuuint64_t)Kdim * 2};
    cuuint32_t box[2]     = {64u, 128u};
    cuuint32_t es[2]      = {1u, 1u};
    enc(tm, CU_TENSOR_MAP_DATA_TYPE_FLOAT16, 2, base, dims, strides, box, es,
        CU_TENSOR_MAP_INTERLEAVE_NONE, CU_TENSOR_MAP_SWIZZLE_128B,
        CU_TENSOR_MAP_L2_PROMOTION_L2_128B, CU_TENSOR_MAP_FLOAT_OOB_FILL_NONE);
}

extern "C" void kernel_launch(void* const* d_in, const int* in_sizes, int n_in,
                              void* d_out, int out_size) {
    const float* noisy = (const float*)d_in[0];
    const float* W1 = (const float*)d_in[1];
    const float* b1 = (const float*)d_in[2];
    const float* W2 = (const float*)d_in[3];
    const float* b2 = (const float*)d_in[4];
    const float* W3 = (const float*)d_in[5];
    const float* b3 = (const float*)d_in[6];
    float* out = (float*)d_out;

    __half *inph, *devh, *W1h, *W2h, *W3h;
    float *Qarr;
    cudaGetSymbolAddress((void**)&inph, g_inph);
    cudaGetSymbolAddress((void**)&devh, g_devh);
    cudaGetSymbolAddress((void**)&Qarr, g_Q);
    cudaGetSymbolAddress((void**)&W1h,  g_W1h);
    cudaGetSymbolAddress((void**)&W2h,  g_W2h);
    cudaGetSymbolAddress((void**)&W3h,  g_W3h);

    static EncodeFn enc = nullptr;
    static cudaStream_t s2 = nullptr;
    static cudaEvent_t forkEv = nullptr;
    static cudaEvent_t fEv[Tv];
    if (!enc) {
        void* p = nullptr;
        cudaDriverEntryPointQueryResult st;
        cudaGetDriverEntryPoint("cuTensorMapEncodeTiled", &p, cudaEnableDefault, &st);
        enc = (EncodeFn)p;
        cudaStreamCreateWithFlags(&s2, cudaStreamNonBlocking);
        cudaEventCreateWithFlags(&forkEv, cudaEventDisableTiming);
        for (int i = 0; i < Tv; ++i)
            cudaEventCreateWithFlags(&fEv[i], cudaEventDisableTiming);
    }

    CUtensorMap tA1, tB1, tB2, tB3;
    make_map_h(enc, &tA1, inph, INFv, Bv);
    make_map_h(enc, &tB1, W1h,  INFv, HIDv);
    make_map_h(enc, &tB2, W2h,  HIDv, HIDv);
    make_map_h(enc, &tB3, W3h,  HIDv, OUTFv);

    const int SMEM_SZ = 1024 + 4 * (3 * 16384);   // 197632
    static bool attr_set = false;
    if (!attr_set) {
        cudaFuncSetAttribute(fused123, cudaFuncAttributeMaxDynamicSharedMemorySize, SMEM_SZ);
        attr_set = true;
    }

    dim3 tb(32, 8);
    transpose_kernel<<<dim3(INFv/32, HIDv/32),  tb>>>(W1, W1h, INFv, HIDv);
    transpose_kernel<<<dim3(HIDv/32, HIDv/32),  tb>>>(W2, W2h, HIDv, HIDv);
    transpose_kernel<<<dim3(HIDv/32, OUTFv/32), tb>>>(W3, W3h, HIDv, OUTFv);

    const int VBLK8 = (Bv * 72) / 512;   // 2304
    init_kernel<<<VBLK8, 512>>>(noisy);

    // fork second stream off the origin stream (flags zeroed by init)
    cudaEventRecord(forkEv, 0);
    cudaStreamWaitEvent(s2, forkEv, 0);

    for (int n = 0; n < Tv; ++n) {
        if (n > 0) cudaStreamWaitEvent(0, fEv[n - 1], 0);    // dev(n-1), Q(n-1) ready
        step_kernel<<<NCTA * SUBS, 256>>>(n);                // origin stream, small blocks
        fused123<<<NCTA, 512, SMEM_SZ, s2>>>(tA1, tB1, tB2, tB3, b1, b2, b3,
                                             devh, Qarr + n, n);  // overlaps step(n)
        cudaEventRecord(fEv[n], s2);
    }
    cudaStreamWaitEvent(0, fEv[Tv - 1], 0);   // join
    finalize_kernel<<<VBLK8, 512>>>(out);
}